// round 6
// baseline (speedup 1.0000x reference)
#include <cuda_runtime.h>
#include <cuda_bf16.h>
#include <cfloat>
#include <cstdint>
#include <cstddef>

// Problem dims
#define BATCH   2
#define SLEN    2048
#define HID     2048
#define NHEADS  16
#define HDIM    128
#define H3      6144
#define MROWS   4096
#define SOFTMAX_SCALE 0.08838834764831845f   // 1/sqrt(128)

// ---------------- scratch (static device arrays; no allocations) -------------
__device__ __nv_bfloat16 g_ph[(size_t)MROWS * H3];    // proj hi (bf16)
__device__ __nv_bfloat16 g_pl[(size_t)MROWS * H3];    // proj lo
__device__ __nv_bfloat16 g_ch[(size_t)MROWS * HID];   // ctx hi
__device__ __nv_bfloat16 g_cl[(size_t)MROWS * HID];   // ctx lo
__device__ __nv_bfloat16 g_ah[(size_t)MROWS * HID];   // gemm A hi
__device__ __nv_bfloat16 g_al[(size_t)MROWS * HID];
__device__ __nv_bfloat16 g_bh[(size_t)H3 * HID];      // gemm B hi
__device__ __nv_bfloat16 g_bl[(size_t)H3 * HID];

// ===================== small PTX helpers =====================================
__device__ __forceinline__ uint32_t smem_u32(const void* p) {
    uint32_t a;
    asm("{ .reg .u64 t; cvta.to.shared.u64 t, %1; cvt.u32.u64 %0, t; }"
        : "=r"(a) : "l"(p));
    return a;
}
__device__ __forceinline__ void cp_async16(uint32_t saddr, const void* gaddr) {
    asm volatile("cp.async.cg.shared.global [%0], [%1], 16;"
                 :: "r"(saddr), "l"(gaddr) : "memory");
}
__device__ __forceinline__ void cp_commit() {
    asm volatile("cp.async.commit_group;" ::: "memory");
}
template <int N>
__device__ __forceinline__ void cp_wait() {
    asm volatile("cp.async.wait_group %0;" :: "n"(N) : "memory");
}
__device__ __forceinline__ void ldsm_x4(uint32_t* r, uint32_t addr) {
    asm volatile("ldmatrix.sync.aligned.m8n8.x4.shared.b16 {%0,%1,%2,%3}, [%4];"
                 : "=r"(r[0]), "=r"(r[1]), "=r"(r[2]), "=r"(r[3]) : "r"(addr));
}
__device__ __forceinline__ void ldsm_x4_t(uint32_t* r, uint32_t addr) {
    asm volatile("ldmatrix.sync.aligned.m8n8.x4.trans.shared.b16 {%0,%1,%2,%3}, [%4];"
                 : "=r"(r[0]), "=r"(r[1]), "=r"(r[2]), "=r"(r[3]) : "r"(addr));
}
__device__ __forceinline__ void mma16816(float* c, const uint32_t* a, const uint32_t* b) {
    asm volatile(
        "mma.sync.aligned.m16n8k16.row.col.f32.bf16.bf16.f32 "
        "{%0,%1,%2,%3}, {%4,%5,%6,%7}, {%8,%9}, {%0,%1,%2,%3};"
        : "+f"(c[0]), "+f"(c[1]), "+f"(c[2]), "+f"(c[3])
        : "r"(a[0]), "r"(a[1]), "r"(a[2]), "r"(a[3]), "r"(b[0]), "r"(b[1]));
}
__device__ __forceinline__ void split2(float a, float b, uint32_t& hi, uint32_t& lo) {
    __nv_bfloat16 ha = __float2bfloat16_rn(a);
    __nv_bfloat16 hb = __float2bfloat16_rn(b);
    __nv_bfloat16 la = __float2bfloat16_rn(a - __bfloat162float(ha));
    __nv_bfloat16 lb = __float2bfloat16_rn(b - __bfloat162float(hb));
    __nv_bfloat162 h2 = __nv_bfloat162(ha, hb);
    __nv_bfloat162 l2 = __nv_bfloat162(la, lb);
    hi = *(uint32_t*)&h2;
    lo = *(uint32_t*)&l2;
}

// ================= fp32 -> bf16 hi/lo split (elementwise) ====================
__global__ __launch_bounds__(256)
void split_kernel(const float* __restrict__ src, __nv_bfloat16* __restrict__ hi,
                  __nv_bfloat16* __restrict__ lo, int n)
{
    int i4 = blockIdx.x * blockDim.x + threadIdx.x;
    if (i4 * 4 >= n) return;
    float4 v = *(const float4*)(src + i4 * 4);
    uint32_t h0, l0, h1, l1;
    split2(v.x, v.y, h0, l0);
    split2(v.z, v.w, h1, l1);
    *(uint2*)(hi + i4 * 4) = make_uint2(h0, h1);
    *(uint2*)(lo + i4 * 4) = make_uint2(l0, l1);
}

// ========== tensor-core GEMM: C[M,N] = A[M,K] * B[N,K]^T =====================
// OM=0: fp32 C.   OM=1: bf16 hi/lo C.
// BM=BN=128, BK=32, 256 thr, 8 warps 4x2, 3-stage cp.async pipeline.
// MMA order: product-index OUTER so consecutive MMAs hit distinct accumulators.
#define GBM 128
#define GBN 128
#define GBK 32
#define MAT_BYTES 8192
#define STAGE_BYTES 32768
#define GT_SMEM (3 * STAGE_BYTES)

template <int OM>
__global__ __launch_bounds__(256, 1)
void gemm_bf16s(const __nv_bfloat16* __restrict__ Ah, const __nv_bfloat16* __restrict__ Al,
                const __nv_bfloat16* __restrict__ Bh, const __nv_bfloat16* __restrict__ Bl,
                float* __restrict__ C, __nv_bfloat16* __restrict__ Ch,
                __nv_bfloat16* __restrict__ Cl, int N, int K)
{
    extern __shared__ char sm[];
    const uint32_t sbase = smem_u32(sm);
    const int tid  = threadIdx.x;
    const int wid  = tid >> 5;
    const int lane = tid & 31;
    const int bx = blockIdx.x;
    const int by = blockIdx.y;
    const int wm = wid >> 1;
    const int wn = wid & 1;

    const __nv_bfloat16* gsrc[4] = {
        Ah + (size_t)by * GBM * K, Al + (size_t)by * GBM * K,
        Bh + (size_t)bx * GBN * K, Bl + (size_t)bx * GBN * K };

    auto prefetch = [&](int c) {
        const uint32_t sst = sbase + (uint32_t)(c % 3) * STAGE_BYTES;
        const int k0 = c * GBK;
#pragma unroll
        for (int i = 0; i < 8; i++) {
            int idx = i * 256 + tid;
            int mat = idx >> 9;
            int within = idx & 511;
            int kc  = within >> 7;
            int row = within & 127;
            const __nv_bfloat16* g = gsrc[mat] + (size_t)row * K + k0 + kc * 8;
            uint32_t s = sst + mat * MAT_BYTES + kc * 2048 + row * 16;
            cp_async16(s, g);
        }
        cp_commit();
    };

    const int subA = lane >> 3;
    const int rowoffA = (lane & 7) + (subA & 1) * 8;
    const int kcselA  = subA >> 1;
    const int rowoffB = (lane & 7) + ((lane >> 4) * 8);
    const int kcselB  = (lane >> 3) & 1;

    float acc[2][8][4];
#pragma unroll
    for (int mt = 0; mt < 2; mt++)
#pragma unroll
        for (int nt = 0; nt < 8; nt++)
#pragma unroll
            for (int q = 0; q < 4; q++) acc[mt][nt][q] = 0.f;

    const int KC = K / GBK;
    prefetch(0);
    prefetch(1);

    for (int c = 0; c < KC; c++) {
        cp_wait<1>();
        __syncthreads();
        if (c + 2 < KC) prefetch(c + 2);

        const uint32_t sst = sbase + (uint32_t)(c % 3) * STAGE_BYTES;
        const uint32_t aBaseHi = sst + 0 * MAT_BYTES;
        const uint32_t aBaseLo = sst + 1 * MAT_BYTES;
        const uint32_t bBaseHi = sst + 2 * MAT_BYTES;
        const uint32_t bBaseLo = sst + 3 * MAT_BYTES;

#pragma unroll
        for (int ks = 0; ks < 2; ks++) {
            uint32_t ah[2][4], al[2][4], bh[4][4], bl[4][4];
#pragma unroll
            for (int mt = 0; mt < 2; mt++) {
                uint32_t roff = (uint32_t)((ks * 2 + kcselA) * 2048 +
                                           (wm * 32 + mt * 16 + rowoffA) * 16);
                ldsm_x4(ah[mt], aBaseHi + roff);
                ldsm_x4(al[mt], aBaseLo + roff);
            }
#pragma unroll
            for (int np = 0; np < 4; np++) {
                uint32_t roff = (uint32_t)((ks * 2 + kcselB) * 2048 +
                                           (wn * 64 + np * 16 + rowoffB) * 16);
                ldsm_x4(bh[np], bBaseHi + roff);
                ldsm_x4(bl[np], bBaseLo + roff);
            }
            // product index OUTER: 16 independent accumulators between reuses
#pragma unroll
            for (int p = 0; p < 3; p++)
#pragma unroll
                for (int mt = 0; mt < 2; mt++)
#pragma unroll
                    for (int nt = 0; nt < 8; nt++) {
                        const uint32_t* ap = (p == 2) ? al[mt] : ah[mt];
                        const uint32_t* bp = (p == 1) ? &bl[nt >> 1][(nt & 1) * 2]
                                                      : &bh[nt >> 1][(nt & 1) * 2];
                        mma16816(acc[mt][nt], ap, bp);
                    }
        }
        __syncthreads();
    }

    const int g  = lane >> 2;
    const int t2 = (lane & 3) * 2;
#pragma unroll
    for (int mt = 0; mt < 2; mt++) {
        int row0 = by * GBM + wm * 32 + mt * 16 + g;
#pragma unroll
        for (int nt = 0; nt < 8; nt++) {
            int col = bx * GBN + wn * 64 + nt * 8 + t2;
            if (OM == 0) {
                *(float2*)(C + (size_t)row0 * N + col) =
                    make_float2(acc[mt][nt][0], acc[mt][nt][1]);
                *(float2*)(C + (size_t)(row0 + 8) * N + col) =
                    make_float2(acc[mt][nt][2], acc[mt][nt][3]);
            } else {
                uint32_t h0, l0, h1, l1;
                split2(acc[mt][nt][0], acc[mt][nt][1], h0, l0);
                split2(acc[mt][nt][2], acc[mt][nt][3], h1, l1);
                *(uint32_t*)(Ch + (size_t)row0 * N + col) = h0;
                *(uint32_t*)(Cl + (size_t)row0 * N + col) = l0;
                *(uint32_t*)(Ch + (size_t)(row0 + 8) * N + col) = h1;
                *(uint32_t*)(Cl + (size_t)(row0 + 8) * N + col) = l1;
            }
        }
    }
}

// ============== tensor-core causal flash attention (bf16 hi/lo in) ===========
#define FA_SMEM 98304

__global__ __launch_bounds__(128, 1)
void flash_tc(const __nv_bfloat16* __restrict__ ph, const __nv_bfloat16* __restrict__ pl,
              __nv_bfloat16* __restrict__ ch, __nv_bfloat16* __restrict__ cl)
{
    extern __shared__ char smc[];
    const uint32_t sb = smem_u32(smc);
    const uint32_t sQH = sb,          sQL = sb + 16384;
    const uint32_t sKH = sb + 32768,  sKL = sb + 49152;
    const uint32_t sVH = sb + 65536,  sVL = sb + 81920;

    const int tid  = threadIdx.x;
    const int lane = tid & 31;
    const int wm   = tid >> 5;
    const int q0   = (int)(gridDim.x - 1 - blockIdx.x) * 64;
    const int h    = blockIdx.y;
    const int b    = blockIdx.z;
    const int g    = lane >> 2;
    const int t2   = (lane & 3) * 2;

    const size_t rowbase = (size_t)(b * SLEN) * H3 + h * HDIM;

    // ---- Q loads (group 0) ----
#pragma unroll
    for (int i = 0; i < 16; i++) {
        int item = i * 128 + tid;
        int mat = item >> 10;
        int within = item & 1023;
        int kcg = within >> 6;
        int row = within & 63;
        const __nv_bfloat16* src = (mat ? pl : ph) + rowbase + (size_t)(q0 + row) * H3 + kcg * 8;
        cp_async16((mat ? sQL : sQH) + kcg * 1024 + row * 16, src);
    }
    cp_commit();
    // ---- K tile 0 (group 1) ----
#pragma unroll
    for (int i = 0; i < 16; i++) {
        int item = i * 128 + tid;
        int mat = item >> 10;
        int within = item & 1023;
        int kcg = within >> 6;
        int row = within & 63;
        const __nv_bfloat16* src = (mat ? pl : ph) + rowbase + (size_t)row * H3 + HID + kcg * 8;
        cp_async16((mat ? sKL : sKH) + kcg * 1024 + row * 16, src);
    }
    cp_commit();

    cp_wait<1>();
    __syncthreads();

    const int rowoffA = (lane & 7) + ((lane >> 3) & 1) * 8;
    const int kcselA  = lane >> 4;
    const int rowoffB = (lane & 7) + (lane >> 4) * 8;
    const int kcselB  = (lane >> 3) & 1;

    uint32_t qh[8][4], ql[8][4];
#pragma unroll
    for (int k = 0; k < 8; k++) {
        uint32_t roff = (uint32_t)((2 * k + kcselA) * 1024 + (wm * 16 + rowoffA) * 16);
        ldsm_x4(qh[k], sQH + roff);
        ldsm_x4(ql[k], sQL + roff);
    }

    float m1 = -FLT_MAX, m2 = -FLT_MAX, l1 = 0.f, l2 = 0.f;
    float o[16][4];
#pragma unroll
    for (int nt = 0; nt < 16; nt++)
#pragma unroll
        for (int q = 0; q < 4; q++) o[nt][q] = 0.f;

    for (int k0 = 0; k0 <= q0; k0 += 64) {
        // ---- V loads for this tile ----
#pragma unroll
        for (int i = 0; i < 16; i++) {
            int item = i * 128 + tid;
            int mat = item >> 10;
            int within = item & 1023;
            int kcg = within >> 6;
            int row = within & 63;
            const __nv_bfloat16* src = (mat ? pl : ph) + rowbase +
                                       (size_t)(k0 + row) * H3 + 2 * HID + kcg * 8;
            cp_async16((mat ? sVL : sVH) + kcg * 1024 + row * 16, src);
        }
        cp_commit();

        cp_wait<1>();      // K ready
        __syncthreads();

        // ---- S = Q K^T, product-outer MMA order ----
        float s[8][4];
#pragma unroll
        for (int nt = 0; nt < 8; nt++)
#pragma unroll
            for (int q = 0; q < 4; q++) s[nt][q] = 0.f;

#pragma unroll
        for (int k = 0; k < 8; k++) {
#pragma unroll
            for (int npp = 0; npp < 2; npp++) {
                uint32_t kh4[2][4], kl4[2][4];
#pragma unroll
                for (int j = 0; j < 2; j++) {
                    int np = npp * 2 + j;
                    uint32_t roff = (uint32_t)((2 * k + kcselB) * 1024 +
                                               (np * 16 + rowoffB) * 16);
                    ldsm_x4(kh4[j], sKH + roff);
                    ldsm_x4(kl4[j], sKL + roff);
                }
#pragma unroll
                for (int p = 0; p < 3; p++)
#pragma unroll
                    for (int j = 0; j < 2; j++)
#pragma unroll
                        for (int sub = 0; sub < 2; sub++) {
                            int nt = (npp * 2 + j) * 2 + sub;
                            const uint32_t* ap = (p == 2) ? ql[k] : qh[k];
                            const uint32_t* bp = (p == 1) ? &kl4[j][sub * 2]
                                                          : &kh4[j][sub * 2];
                            mma16816(s[nt], ap, bp);
                        }
            }
        }

        // ---- scale + causal mask ----
#pragma unroll
        for (int nt = 0; nt < 8; nt++)
#pragma unroll
            for (int q = 0; q < 4; q++) s[nt][q] *= SOFTMAX_SCALE;
        if (k0 == q0) {
            int r1 = q0 + wm * 16 + g, r2 = r1 + 8;
#pragma unroll
            for (int nt = 0; nt < 8; nt++) {
                int c0 = k0 + nt * 8 + t2;
                if (c0     > r1) s[nt][0] = -FLT_MAX;
                if (c0 + 1 > r1) s[nt][1] = -FLT_MAX;
                if (c0     > r2) s[nt][2] = -FLT_MAX;
                if (c0 + 1 > r2) s[nt][3] = -FLT_MAX;
            }
        }

        // ---- online softmax ----
        float tm1 = -FLT_MAX, tm2 = -FLT_MAX;
#pragma unroll
        for (int nt = 0; nt < 8; nt++) {
            tm1 = fmaxf(tm1, fmaxf(s[nt][0], s[nt][1]));
            tm2 = fmaxf(tm2, fmaxf(s[nt][2], s[nt][3]));
        }
        tm1 = fmaxf(tm1, __shfl_xor_sync(0xffffffffu, tm1, 1));
        tm1 = fmaxf(tm1, __shfl_xor_sync(0xffffffffu, tm1, 2));
        tm2 = fmaxf(tm2, __shfl_xor_sync(0xffffffffu, tm2, 1));
        tm2 = fmaxf(tm2, __shfl_xor_sync(0xffffffffu, tm2, 2));
        float nm1 = fmaxf(m1, tm1), nm2 = fmaxf(m2, tm2);
        float a1 = __expf(m1 - nm1), a2 = __expf(m2 - nm2);
        m1 = nm1; m2 = nm2;

        float rs1 = 0.f, rs2 = 0.f;
#pragma unroll
        for (int nt = 0; nt < 8; nt++) {
            s[nt][0] = __expf(s[nt][0] - nm1);
            s[nt][1] = __expf(s[nt][1] - nm1);
            s[nt][2] = __expf(s[nt][2] - nm2);
            s[nt][3] = __expf(s[nt][3] - nm2);
            rs1 += s[nt][0] + s[nt][1];
            rs2 += s[nt][2] + s[nt][3];
        }
        rs1 += __shfl_xor_sync(0xffffffffu, rs1, 1);
        rs1 += __shfl_xor_sync(0xffffffffu, rs1, 2);
        rs2 += __shfl_xor_sync(0xffffffffu, rs2, 1);
        rs2 += __shfl_xor_sync(0xffffffffu, rs2, 2);
        l1 = l1 * a1 + rs1;
        l2 = l2 * a2 + rs2;
#pragma unroll
        for (int nt = 0; nt < 16; nt++) {
            o[nt][0] *= a1; o[nt][1] *= a1;
            o[nt][2] *= a2; o[nt][3] *= a2;
        }

        // ---- P -> bf16 hi/lo fragments ----
        uint32_t hp01[8], hp23[8], lp01[8], lp23[8];
#pragma unroll
        for (int nt = 0; nt < 8; nt++) {
            split2(s[nt][0], s[nt][1], hp01[nt], lp01[nt]);
            split2(s[nt][2], s[nt][3], hp23[nt], lp23[nt]);
        }

        cp_wait<0>();       // V ready
        __syncthreads();
        if (k0 + 64 <= q0) {   // prefetch next K during PV
#pragma unroll
            for (int i = 0; i < 16; i++) {
                int item = i * 128 + tid;
                int mat = item >> 10;
                int within = item & 1023;
                int kcg = within >> 6;
                int row = within & 63;
                const __nv_bfloat16* src = (mat ? pl : ph) + rowbase +
                                           (size_t)(k0 + 64 + row) * H3 + HID + kcg * 8;
                cp_async16((mat ? sKL : sKH) + kcg * 1024 + row * 16, src);
            }
            cp_commit();
        }

        // ---- O += P V, product-outer MMA order ----
#pragma unroll
        for (int kt = 0; kt < 4; kt++) {
            uint32_t ah4[4] = {hp01[2*kt], hp23[2*kt], hp01[2*kt+1], hp23[2*kt+1]};
            uint32_t al4[4] = {lp01[2*kt], lp23[2*kt], lp01[2*kt+1], lp23[2*kt+1]};
#pragma unroll
            for (int npp = 0; npp < 4; npp++) {
                uint32_t vh4[2][4], vl4[2][4];
#pragma unroll
                for (int j = 0; j < 2; j++) {
                    int np = npp * 2 + j;
                    uint32_t roff = (uint32_t)((np * 2 + (lane >> 4)) * 1024 +
                                               (kt * 16 + ((lane >> 3) & 1) * 8 + (lane & 7)) * 16);
                    ldsm_x4_t(vh4[j], sVH + roff);
                    ldsm_x4_t(vl4[j], sVL + roff);
                }
#pragma unroll
                for (int p = 0; p < 3; p++)
#pragma unroll
                    for (int j = 0; j < 2; j++)
#pragma unroll
                        for (int sub = 0; sub < 2; sub++) {
                            int nt = (npp * 2 + j) * 2 + sub;
                            const uint32_t* ap = (p == 2) ? al4 : ah4;
                            const uint32_t* bp = (p == 1) ? &vl4[j][sub * 2]
                                                          : &vh4[j][sub * 2];
                            mma16816(o[nt], ap, bp);
                        }
            }
        }
        __syncthreads();
    }

    // ---- finalize: write ctx as bf16 hi/lo ----
    float inv1 = 1.f / l1, inv2 = 1.f / l2;
    int r1 = q0 + wm * 16 + g;
    size_t base1 = (size_t)(b * SLEN + r1) * HID + h * HDIM;
    size_t base2 = base1 + 8 * HID;
#pragma unroll
    for (int nt = 0; nt < 16; nt++) {
        int col = nt * 8 + t2;
        uint32_t h0, l0, h1, l1w;
        split2(o[nt][0] * inv1, o[nt][1] * inv1, h0, l0);
        split2(o[nt][2] * inv2, o[nt][3] * inv2, h1, l1w);
        *(uint32_t*)(ch + base1 + col) = h0;
        *(uint32_t*)(cl + base1 + col) = l0;
        *(uint32_t*)(ch + base2 + col) = h1;
        *(uint32_t*)(cl + base2 + col) = l1w;
    }
}

// ============================ host entry =====================================
extern "C" void kernel_launch(void* const* d_in, const int* in_sizes, int n_in,
                              void* d_out, int out_size)
{
    const float* hidden = (const float*)d_in[0];
    const float* w_pack = (const float*)d_in[2];
    const float* w_o    = (const float*)d_in[3];
    float* out = (float*)d_out;

    __nv_bfloat16 *ph, *pl, *ch, *cl, *ah, *al, *bh, *bl;
    cudaGetSymbolAddress((void**)&ph, g_ph);
    cudaGetSymbolAddress((void**)&pl, g_pl);
    cudaGetSymbolAddress((void**)&ch, g_ch);
    cudaGetSymbolAddress((void**)&cl, g_cl);
    cudaGetSymbolAddress((void**)&ah, g_ah);
    cudaGetSymbolAddress((void**)&al, g_al);
    cudaGetSymbolAddress((void**)&bh, g_bh);
    cudaGetSymbolAddress((void**)&bl, g_bl);

    static bool attr_set = false;
    if (!attr_set) {
        cudaFuncSetAttribute(gemm_bf16s<0>, cudaFuncAttributeMaxDynamicSharedMemorySize, GT_SMEM);
        cudaFuncSetAttribute(gemm_bf16s<1>, cudaFuncAttributeMaxDynamicSharedMemorySize, GT_SMEM);
        cudaFuncSetAttribute(flash_tc,      cudaFuncAttributeMaxDynamicSharedMemorySize, FA_SMEM);
        attr_set = true;
    }

    // 1) split QKV inputs
    split_kernel<<<MROWS * HID / 4 / 256, 256>>>(hidden, ah, al, MROWS * HID);
    split_kernel<<<H3 * HID / 4 / 256, 256>>>(w_pack, bh, bl, H3 * HID);

    // 2) QKV projection -> bf16 hi/lo proj
    gemm_bf16s<1><<<dim3(H3 / GBN, MROWS / GBM), 256, GT_SMEM>>>(
        ah, al, bh, bl, nullptr, ph, pl, H3, HID);

    // 3) causal flash attention -> bf16 hi/lo ctx
    flash_tc<<<dim3(SLEN / 64, NHEADS, BATCH), 128, FA_SMEM>>>(ph, pl, ch, cl);

    // 4) split w_o, output projection -> fp32 out
    split_kernel<<<HID * HID / 4 / 256, 256>>>(w_o, bh, bl, HID * HID);
    gemm_bf16s<0><<<dim3(HID / GBN, MROWS / GBM), 256, GT_SMEM>>>(
        ch, cl, bh, bl, out, nullptr, nullptr, HID, HID);
}

// round 7
// speedup vs baseline: 1.5308x; 1.5308x over previous
#include <cuda_runtime.h>
#include <cuda_bf16.h>
#include <cfloat>
#include <cstdint>
#include <cstddef>

// Problem dims
#define BATCH   2
#define SLEN    2048
#define HID     2048
#define NHEADS  16
#define HDIM    128
#define H3      6144
#define MROWS   4096
#define SOFTMAX_SCALE 0.08838834764831845f   // 1/sqrt(128)

// ---------------- scratch (static device arrays; no allocations) -------------
__device__ __nv_bfloat16 g_ph[(size_t)MROWS * H3];    // proj hi (bf16)
__device__ __nv_bfloat16 g_pl[(size_t)MROWS * H3];    // proj lo
__device__ __nv_bfloat16 g_ch[(size_t)MROWS * HID];   // ctx hi
__device__ __nv_bfloat16 g_cl[(size_t)MROWS * HID];   // ctx lo
__device__ __nv_bfloat16 g_ah[(size_t)MROWS * HID];   // gemm A hi
__device__ __nv_bfloat16 g_al[(size_t)MROWS * HID];
__device__ __nv_bfloat16 g_bh[(size_t)H3 * HID];      // gemm B hi
__device__ __nv_bfloat16 g_bl[(size_t)H3 * HID];

// ===================== small PTX helpers =====================================
__device__ __forceinline__ uint32_t smem_u32(const void* p) {
    uint32_t a;
    asm("{ .reg .u64 t; cvta.to.shared.u64 t, %1; cvt.u32.u64 %0, t; }"
        : "=r"(a) : "l"(p));
    return a;
}
__device__ __forceinline__ void cp_async16(uint32_t saddr, const void* gaddr) {
    asm volatile("cp.async.cg.shared.global [%0], [%1], 16;"
                 :: "r"(saddr), "l"(gaddr) : "memory");
}
__device__ __forceinline__ void cp_commit() {
    asm volatile("cp.async.commit_group;" ::: "memory");
}
template <int N>
__device__ __forceinline__ void cp_wait() {
    asm volatile("cp.async.wait_group %0;" :: "n"(N) : "memory");
}
__device__ __forceinline__ void ldsm_x4(uint32_t* r, uint32_t addr) {
    asm volatile("ldmatrix.sync.aligned.m8n8.x4.shared.b16 {%0,%1,%2,%3}, [%4];"
                 : "=r"(r[0]), "=r"(r[1]), "=r"(r[2]), "=r"(r[3]) : "r"(addr));
}
__device__ __forceinline__ void ldsm_x4_t(uint32_t* r, uint32_t addr) {
    asm volatile("ldmatrix.sync.aligned.m8n8.x4.trans.shared.b16 {%0,%1,%2,%3}, [%4];"
                 : "=r"(r[0]), "=r"(r[1]), "=r"(r[2]), "=r"(r[3]) : "r"(addr));
}
__device__ __forceinline__ void mma16816(float* c, const uint32_t* a, const uint32_t* b) {
    asm volatile(
        "mma.sync.aligned.m16n8k16.row.col.f32.bf16.bf16.f32 "
        "{%0,%1,%2,%3}, {%4,%5,%6,%7}, {%8,%9}, {%0,%1,%2,%3};"
        : "+f"(c[0]), "+f"(c[1]), "+f"(c[2]), "+f"(c[3])
        : "r"(a[0]), "r"(a[1]), "r"(a[2]), "r"(a[3]), "r"(b[0]), "r"(b[1]));
}
__device__ __forceinline__ void split2(float a, float b, uint32_t& hi, uint32_t& lo) {
    __nv_bfloat16 ha = __float2bfloat16_rn(a);
    __nv_bfloat16 hb = __float2bfloat16_rn(b);
    __nv_bfloat16 la = __float2bfloat16_rn(a - __bfloat162float(ha));
    __nv_bfloat16 lb = __float2bfloat16_rn(b - __bfloat162float(hb));
    __nv_bfloat162 h2 = __nv_bfloat162(ha, hb);
    __nv_bfloat162 l2 = __nv_bfloat162(la, lb);
    hi = *(uint32_t*)&h2;
    lo = *(uint32_t*)&l2;
}

// ================= fp32 -> bf16 hi/lo split (elementwise) ====================
__global__ __launch_bounds__(256)
void split_kernel(const float* __restrict__ src, __nv_bfloat16* __restrict__ hi,
                  __nv_bfloat16* __restrict__ lo, int n)
{
    int i4 = blockIdx.x * blockDim.x + threadIdx.x;
    if (i4 * 4 >= n) return;
    float4 v = *(const float4*)(src + i4 * 4);
    uint32_t h0, l0, h1, l1;
    split2(v.x, v.y, h0, l0);
    split2(v.z, v.w, h1, l1);
    *(uint2*)(hi + i4 * 4) = make_uint2(h0, h1);
    *(uint2*)(lo + i4 * 4) = make_uint2(l0, l1);
}

// ========== tensor-core GEMM: C[M,N] = A[M,K] * B[N,K]^T =====================
// OM=0: fp32 C.   OM=1: bf16 hi/lo C.
// BM=BN=128, BK=32, 256 thr, 8 warps 4x2, 3-stage cp.async pipeline.
// Inner MMA order: p x j round-robin over 2 accumulators (reuse distance 2),
// fragment loads identical to the R5 layout (register-neutral).
#define GBM 128
#define GBN 128
#define GBK 32
#define MAT_BYTES 8192
#define STAGE_BYTES 32768
#define GT_SMEM (3 * STAGE_BYTES)

template <int OM>
__global__ __launch_bounds__(256, 1)
void gemm_bf16s(const __nv_bfloat16* __restrict__ Ah, const __nv_bfloat16* __restrict__ Al,
                const __nv_bfloat16* __restrict__ Bh, const __nv_bfloat16* __restrict__ Bl,
                float* __restrict__ C, __nv_bfloat16* __restrict__ Ch,
                __nv_bfloat16* __restrict__ Cl, int N, int K)
{
    extern __shared__ char sm[];
    const uint32_t sbase = smem_u32(sm);
    const int tid  = threadIdx.x;
    const int wid  = tid >> 5;
    const int lane = tid & 31;
    const int bx = blockIdx.x;
    const int by = blockIdx.y;
    const int wm = wid >> 1;
    const int wn = wid & 1;

    const __nv_bfloat16* gsrc[4] = {
        Ah + (size_t)by * GBM * K, Al + (size_t)by * GBM * K,
        Bh + (size_t)bx * GBN * K, Bl + (size_t)bx * GBN * K };

    auto prefetch = [&](int c) {
        const uint32_t sst = sbase + (uint32_t)(c % 3) * STAGE_BYTES;
        const int k0 = c * GBK;
#pragma unroll
        for (int i = 0; i < 8; i++) {
            int idx = i * 256 + tid;
            int mat = idx >> 9;
            int within = idx & 511;
            int kc  = within >> 7;
            int row = within & 127;
            const __nv_bfloat16* g = gsrc[mat] + (size_t)row * K + k0 + kc * 8;
            uint32_t s = sst + mat * MAT_BYTES + kc * 2048 + row * 16;
            cp_async16(s, g);
        }
        cp_commit();
    };

    const int subA = lane >> 3;
    const int rowoffA = (lane & 7) + (subA & 1) * 8;
    const int kcselA  = subA >> 1;
    const int rowoffB = (lane & 7) + ((lane >> 4) * 8);
    const int kcselB  = (lane >> 3) & 1;

    float acc[2][8][4];
#pragma unroll
    for (int mt = 0; mt < 2; mt++)
#pragma unroll
        for (int nt = 0; nt < 8; nt++)
#pragma unroll
            for (int q = 0; q < 4; q++) acc[mt][nt][q] = 0.f;

    const int KC = K / GBK;
    prefetch(0);
    prefetch(1);

    for (int c = 0; c < KC; c++) {
        cp_wait<1>();
        __syncthreads();
        if (c + 2 < KC) prefetch(c + 2);

        const uint32_t sst = sbase + (uint32_t)(c % 3) * STAGE_BYTES;
        const uint32_t aBaseHi = sst + 0 * MAT_BYTES;
        const uint32_t aBaseLo = sst + 1 * MAT_BYTES;
        const uint32_t bBaseHi = sst + 2 * MAT_BYTES;
        const uint32_t bBaseLo = sst + 3 * MAT_BYTES;

#pragma unroll
        for (int ks = 0; ks < 2; ks++) {
            uint32_t ah[2][4], al[2][4], bh[4][4], bl[4][4];
#pragma unroll
            for (int mt = 0; mt < 2; mt++) {
                uint32_t roff = (uint32_t)((ks * 2 + kcselA) * 2048 +
                                           (wm * 32 + mt * 16 + rowoffA) * 16);
                ldsm_x4(ah[mt], aBaseHi + roff);
                ldsm_x4(al[mt], aBaseLo + roff);
            }
#pragma unroll
            for (int np = 0; np < 4; np++) {
                uint32_t roff = (uint32_t)((ks * 2 + kcselB) * 2048 +
                                           (wn * 64 + np * 16 + rowoffB) * 16);
                ldsm_x4(bh[np], bBaseHi + roff);
                ldsm_x4(bl[np], bBaseLo + roff);
            }
            // p x j round-robin: consecutive MMAs hit different accumulators
#pragma unroll
            for (int mt = 0; mt < 2; mt++)
#pragma unroll
                for (int np = 0; np < 4; np++)
#pragma unroll
                    for (int p = 0; p < 3; p++)
#pragma unroll
                        for (int j = 0; j < 2; j++) {
                            const uint32_t* ap = (p == 2) ? al[mt] : ah[mt];
                            const uint32_t* bp = (p == 1) ? &bl[np][j * 2]
                                                          : &bh[np][j * 2];
                            mma16816(acc[mt][np * 2 + j], ap, bp);
                        }
        }
        __syncthreads();
    }

    const int g  = lane >> 2;
    const int t2 = (lane & 3) * 2;
#pragma unroll
    for (int mt = 0; mt < 2; mt++) {
        int row0 = by * GBM + wm * 32 + mt * 16 + g;
#pragma unroll
        for (int nt = 0; nt < 8; nt++) {
            int col = bx * GBN + wn * 64 + nt * 8 + t2;
            if (OM == 0) {
                *(float2*)(C + (size_t)row0 * N + col) =
                    make_float2(acc[mt][nt][0], acc[mt][nt][1]);
                *(float2*)(C + (size_t)(row0 + 8) * N + col) =
                    make_float2(acc[mt][nt][2], acc[mt][nt][3]);
            } else {
                uint32_t h0, l0, h1, l1;
                split2(acc[mt][nt][0], acc[mt][nt][1], h0, l0);
                split2(acc[mt][nt][2], acc[mt][nt][3], h1, l1);
                *(uint32_t*)(Ch + (size_t)row0 * N + col) = h0;
                *(uint32_t*)(Cl + (size_t)row0 * N + col) = l0;
                *(uint32_t*)(Ch + (size_t)(row0 + 8) * N + col) = h1;
                *(uint32_t*)(Cl + (size_t)(row0 + 8) * N + col) = l1;
            }
        }
    }
}

// ============== tensor-core causal flash attention (bf16 hi/lo in) ===========
#define FA_SMEM 98304

__global__ __launch_bounds__(128, 1)
void flash_tc(const __nv_bfloat16* __restrict__ ph, const __nv_bfloat16* __restrict__ pl,
              __nv_bfloat16* __restrict__ ch, __nv_bfloat16* __restrict__ cl)
{
    extern __shared__ char smc[];
    const uint32_t sb = smem_u32(smc);
    const uint32_t sQH = sb,          sQL = sb + 16384;
    const uint32_t sKH = sb + 32768,  sKL = sb + 49152;
    const uint32_t sVH = sb + 65536,  sVL = sb + 81920;

    const int tid  = threadIdx.x;
    const int lane = tid & 31;
    const int wm   = tid >> 5;
    const int q0   = (int)(gridDim.x - 1 - blockIdx.x) * 64;
    const int h    = blockIdx.y;
    const int b    = blockIdx.z;
    const int g    = lane >> 2;
    const int t2   = (lane & 3) * 2;

    const size_t rowbase = (size_t)(b * SLEN) * H3 + h * HDIM;

    // ---- Q loads (group 0) ----
#pragma unroll
    for (int i = 0; i < 16; i++) {
        int item = i * 128 + tid;
        int mat = item >> 10;
        int within = item & 1023;
        int kcg = within >> 6;
        int row = within & 63;
        const __nv_bfloat16* src = (mat ? pl : ph) + rowbase + (size_t)(q0 + row) * H3 + kcg * 8;
        cp_async16((mat ? sQL : sQH) + kcg * 1024 + row * 16, src);
    }
    cp_commit();
    // ---- K tile 0 (group 1) ----
#pragma unroll
    for (int i = 0; i < 16; i++) {
        int item = i * 128 + tid;
        int mat = item >> 10;
        int within = item & 1023;
        int kcg = within >> 6;
        int row = within & 63;
        const __nv_bfloat16* src = (mat ? pl : ph) + rowbase + (size_t)row * H3 + HID + kcg * 8;
        cp_async16((mat ? sKL : sKH) + kcg * 1024 + row * 16, src);
    }
    cp_commit();

    cp_wait<1>();
    __syncthreads();

    const int rowoffA = (lane & 7) + ((lane >> 3) & 1) * 8;
    const int kcselA  = lane >> 4;
    const int rowoffB = (lane & 7) + (lane >> 4) * 8;
    const int kcselB  = (lane >> 3) & 1;

    uint32_t qh[8][4], ql[8][4];
#pragma unroll
    for (int k = 0; k < 8; k++) {
        uint32_t roff = (uint32_t)((2 * k + kcselA) * 1024 + (wm * 16 + rowoffA) * 16);
        ldsm_x4(qh[k], sQH + roff);
        ldsm_x4(ql[k], sQL + roff);
    }

    float m1 = -FLT_MAX, m2 = -FLT_MAX, l1 = 0.f, l2 = 0.f;
    float o[16][4];
#pragma unroll
    for (int nt = 0; nt < 16; nt++)
#pragma unroll
        for (int q = 0; q < 4; q++) o[nt][q] = 0.f;

    for (int k0 = 0; k0 <= q0; k0 += 64) {
        // ---- V loads for this tile ----
#pragma unroll
        for (int i = 0; i < 16; i++) {
            int item = i * 128 + tid;
            int mat = item >> 10;
            int within = item & 1023;
            int kcg = within >> 6;
            int row = within & 63;
            const __nv_bfloat16* src = (mat ? pl : ph) + rowbase +
                                       (size_t)(k0 + row) * H3 + 2 * HID + kcg * 8;
            cp_async16((mat ? sVL : sVH) + kcg * 1024 + row * 16, src);
        }
        cp_commit();

        cp_wait<1>();      // K ready
        __syncthreads();

        // ---- S = Q K^T, p x sub round-robin (reuse distance 2) ----
        float s[8][4];
#pragma unroll
        for (int nt = 0; nt < 8; nt++)
#pragma unroll
            for (int q = 0; q < 4; q++) s[nt][q] = 0.f;

#pragma unroll
        for (int k = 0; k < 8; k++) {
#pragma unroll
            for (int np = 0; np < 4; np++) {
                uint32_t roff = (uint32_t)((2 * k + kcselB) * 1024 + (np * 16 + rowoffB) * 16);
                uint32_t kh4[4], kl4[4];
                ldsm_x4(kh4, sKH + roff);
                ldsm_x4(kl4, sKL + roff);
#pragma unroll
                for (int p = 0; p < 3; p++)
#pragma unroll
                    for (int j = 0; j < 2; j++) {
                        const uint32_t* ap = (p == 2) ? ql[k] : qh[k];
                        const uint32_t* bp = (p == 1) ? &kl4[j * 2] : &kh4[j * 2];
                        mma16816(s[np * 2 + j], ap, bp);
                    }
            }
        }

        // ---- scale + causal mask ----
#pragma unroll
        for (int nt = 0; nt < 8; nt++)
#pragma unroll
            for (int q = 0; q < 4; q++) s[nt][q] *= SOFTMAX_SCALE;
        if (k0 == q0) {
            int r1 = q0 + wm * 16 + g, r2 = r1 + 8;
#pragma unroll
            for (int nt = 0; nt < 8; nt++) {
                int c0 = k0 + nt * 8 + t2;
                if (c0     > r1) s[nt][0] = -FLT_MAX;
                if (c0 + 1 > r1) s[nt][1] = -FLT_MAX;
                if (c0     > r2) s[nt][2] = -FLT_MAX;
                if (c0 + 1 > r2) s[nt][3] = -FLT_MAX;
            }
        }

        // ---- online softmax ----
        float tm1 = -FLT_MAX, tm2 = -FLT_MAX;
#pragma unroll
        for (int nt = 0; nt < 8; nt++) {
            tm1 = fmaxf(tm1, fmaxf(s[nt][0], s[nt][1]));
            tm2 = fmaxf(tm2, fmaxf(s[nt][2], s[nt][3]));
        }
        tm1 = fmaxf(tm1, __shfl_xor_sync(0xffffffffu, tm1, 1));
        tm1 = fmaxf(tm1, __shfl_xor_sync(0xffffffffu, tm1, 2));
        tm2 = fmaxf(tm2, __shfl_xor_sync(0xffffffffu, tm2, 1));
        tm2 = fmaxf(tm2, __shfl_xor_sync(0xffffffffu, tm2, 2));
        float nm1 = fmaxf(m1, tm1), nm2 = fmaxf(m2, tm2);
        float a1 = __expf(m1 - nm1), a2 = __expf(m2 - nm2);
        m1 = nm1; m2 = nm2;

        float rs1 = 0.f, rs2 = 0.f;
#pragma unroll
        for (int nt = 0; nt < 8; nt++) {
            s[nt][0] = __expf(s[nt][0] - nm1);
            s[nt][1] = __expf(s[nt][1] - nm1);
            s[nt][2] = __expf(s[nt][2] - nm2);
            s[nt][3] = __expf(s[nt][3] - nm2);
            rs1 += s[nt][0] + s[nt][1];
            rs2 += s[nt][2] + s[nt][3];
        }
        rs1 += __shfl_xor_sync(0xffffffffu, rs1, 1);
        rs1 += __shfl_xor_sync(0xffffffffu, rs1, 2);
        rs2 += __shfl_xor_sync(0xffffffffu, rs2, 1);
        rs2 += __shfl_xor_sync(0xffffffffu, rs2, 2);
        l1 = l1 * a1 + rs1;
        l2 = l2 * a2 + rs2;
#pragma unroll
        for (int nt = 0; nt < 16; nt++) {
            o[nt][0] *= a1; o[nt][1] *= a1;
            o[nt][2] *= a2; o[nt][3] *= a2;
        }

        // ---- P -> bf16 hi/lo fragments ----
        uint32_t hp01[8], hp23[8], lp01[8], lp23[8];
#pragma unroll
        for (int nt = 0; nt < 8; nt++) {
            split2(s[nt][0], s[nt][1], hp01[nt], lp01[nt]);
            split2(s[nt][2], s[nt][3], hp23[nt], lp23[nt]);
        }

        cp_wait<0>();       // V ready
        __syncthreads();
        if (k0 + 64 <= q0) {   // prefetch next K during PV
#pragma unroll
            for (int i = 0; i < 16; i++) {
                int item = i * 128 + tid;
                int mat = item >> 10;
                int within = item & 1023;
                int kcg = within >> 6;
                int row = within & 63;
                const __nv_bfloat16* src = (mat ? pl : ph) + rowbase +
                                           (size_t)(k0 + 64 + row) * H3 + HID + kcg * 8;
                cp_async16((mat ? sKL : sKH) + kcg * 1024 + row * 16, src);
            }
            cp_commit();
        }

        // ---- O += P V, p x sub round-robin ----
#pragma unroll
        for (int kt = 0; kt < 4; kt++) {
            uint32_t ah4[4] = {hp01[2*kt], hp23[2*kt], hp01[2*kt+1], hp23[2*kt+1]};
            uint32_t al4[4] = {lp01[2*kt], lp23[2*kt], lp01[2*kt+1], lp23[2*kt+1]};
#pragma unroll
            for (int np = 0; np < 8; np++) {
                uint32_t roff = (uint32_t)((np * 2 + (lane >> 4)) * 1024 +
                                           (kt * 16 + ((lane >> 3) & 1) * 8 + (lane & 7)) * 16);
                uint32_t vh4[4], vl4[4];
                ldsm_x4_t(vh4, sVH + roff);
                ldsm_x4_t(vl4, sVL + roff);
#pragma unroll
                for (int p = 0; p < 3; p++)
#pragma unroll
                    for (int j = 0; j < 2; j++) {
                        const uint32_t* ap = (p == 2) ? al4 : ah4;
                        const uint32_t* bp = (p == 1) ? &vl4[j * 2] : &vh4[j * 2];
                        mma16816(o[np * 2 + j], ap, bp);
                    }
            }
        }
        __syncthreads();
    }

    // ---- finalize: write ctx as bf16 hi/lo ----
    float inv1 = 1.f / l1, inv2 = 1.f / l2;
    int r1 = q0 + wm * 16 + g;
    size_t base1 = (size_t)(b * SLEN + r1) * HID + h * HDIM;
    size_t base2 = base1 + 8 * HID;
#pragma unroll
    for (int nt = 0; nt < 16; nt++) {
        int col = nt * 8 + t2;
        uint32_t h0, l0, h1, l1w;
        split2(o[nt][0] * inv1, o[nt][1] * inv1, h0, l0);
        split2(o[nt][2] * inv2, o[nt][3] * inv2, h1, l1w);
        *(uint32_t*)(ch + base1 + col) = h0;
        *(uint32_t*)(cl + base1 + col) = l0;
        *(uint32_t*)(ch + base2 + col) = h1;
        *(uint32_t*)(cl + base2 + col) = l1w;
    }
}

// ============================ host entry =====================================
extern "C" void kernel_launch(void* const* d_in, const int* in_sizes, int n_in,
                              void* d_out, int out_size)
{
    const float* hidden = (const float*)d_in[0];
    const float* w_pack = (const float*)d_in[2];
    const float* w_o    = (const float*)d_in[3];
    float* out = (float*)d_out;

    __nv_bfloat16 *ph, *pl, *ch, *cl, *ah, *al, *bh, *bl;
    cudaGetSymbolAddress((void**)&ph, g_ph);
    cudaGetSymbolAddress((void**)&pl, g_pl);
    cudaGetSymbolAddress((void**)&ch, g_ch);
    cudaGetSymbolAddress((void**)&cl, g_cl);
    cudaGetSymbolAddress((void**)&ah, g_ah);
    cudaGetSymbolAddress((void**)&al, g_al);
    cudaGetSymbolAddress((void**)&bh, g_bh);
    cudaGetSymbolAddress((void**)&bl, g_bl);

    static bool attr_set = false;
    if (!attr_set) {
        cudaFuncSetAttribute(gemm_bf16s<0>, cudaFuncAttributeMaxDynamicSharedMemorySize, GT_SMEM);
        cudaFuncSetAttribute(gemm_bf16s<1>, cudaFuncAttributeMaxDynamicSharedMemorySize, GT_SMEM);
        cudaFuncSetAttribute(flash_tc,      cudaFuncAttributeMaxDynamicSharedMemorySize, FA_SMEM);
        attr_set = true;
    }

    // 1) split QKV inputs
    split_kernel<<<MROWS * HID / 4 / 256, 256>>>(hidden, ah, al, MROWS * HID);
    split_kernel<<<H3 * HID / 4 / 256, 256>>>(w_pack, bh, bl, H3 * HID);

    // 2) QKV projection -> bf16 hi/lo proj
    gemm_bf16s<1><<<dim3(H3 / GBN, MROWS / GBM), 256, GT_SMEM>>>(
        ah, al, bh, bl, nullptr, ph, pl, H3, HID);

    // 3) causal flash attention -> bf16 hi/lo ctx
    flash_tc<<<dim3(SLEN / 64, NHEADS, BATCH), 128, FA_SMEM>>>(ph, pl, ch, cl);

    // 4) split w_o, output projection -> fp32 out
    split_kernel<<<HID * HID / 4 / 256, 256>>>(w_o, bh, bl, HID * HID);
    gemm_bf16s<0><<<dim3(HID / GBN, MROWS / GBM), 256, GT_SMEM>>>(
        ch, cl, bh, bl, out, nullptr, nullptr, HID, HID);
}

// round 8
// speedup vs baseline: 1.5345x; 1.0024x over previous
#include <cuda_runtime.h>
#include <cuda_bf16.h>
#include <cfloat>
#include <cstdint>
#include <cstddef>

// Problem dims
#define BATCH   2
#define SLEN    2048
#define HID     2048
#define NHEADS  16
#define HDIM    128
#define H3      6144
#define MROWS   4096
#define SOFTMAX_SCALE 0.08838834764831845f   // 1/sqrt(128)

// ---------------- scratch (static device arrays; no allocations) -------------
__device__ __nv_bfloat16 g_ph[(size_t)MROWS * H3];    // proj hi (bf16)
__device__ __nv_bfloat16 g_pl[(size_t)MROWS * H3];    // proj lo
__device__ __nv_bfloat16 g_ch[(size_t)MROWS * HID];   // ctx hi
__device__ __nv_bfloat16 g_cl[(size_t)MROWS * HID];   // ctx lo
__device__ __nv_bfloat16 g_ah[(size_t)MROWS * HID];   // gemm A hi
__device__ __nv_bfloat16 g_al[(size_t)MROWS * HID];
__device__ __nv_bfloat16 g_bh[(size_t)H3 * HID];      // gemm B hi
__device__ __nv_bfloat16 g_bl[(size_t)H3 * HID];

// ===================== small PTX helpers =====================================
__device__ __forceinline__ uint32_t smem_u32(const void* p) {
    uint32_t a;
    asm("{ .reg .u64 t; cvta.to.shared.u64 t, %1; cvt.u32.u64 %0, t; }"
        : "=r"(a) : "l"(p));
    return a;
}
__device__ __forceinline__ void cp_async16(uint32_t saddr, const void* gaddr) {
    asm volatile("cp.async.cg.shared.global [%0], [%1], 16;"
                 :: "r"(saddr), "l"(gaddr) : "memory");
}
__device__ __forceinline__ void cp_commit() {
    asm volatile("cp.async.commit_group;" ::: "memory");
}
template <int N>
__device__ __forceinline__ void cp_wait() {
    asm volatile("cp.async.wait_group %0;" :: "n"(N) : "memory");
}
__device__ __forceinline__ void ldsm_x4(uint32_t* r, uint32_t addr) {
    asm volatile("ldmatrix.sync.aligned.m8n8.x4.shared.b16 {%0,%1,%2,%3}, [%4];"
                 : "=r"(r[0]), "=r"(r[1]), "=r"(r[2]), "=r"(r[3]) : "r"(addr));
}
__device__ __forceinline__ void ldsm_x4_t(uint32_t* r, uint32_t addr) {
    asm volatile("ldmatrix.sync.aligned.m8n8.x4.trans.shared.b16 {%0,%1,%2,%3}, [%4];"
                 : "=r"(r[0]), "=r"(r[1]), "=r"(r[2]), "=r"(r[3]) : "r"(addr));
}
__device__ __forceinline__ void mma16816(float* c, const uint32_t* a, const uint32_t* b) {
    asm volatile(
        "mma.sync.aligned.m16n8k16.row.col.f32.bf16.bf16.f32 "
        "{%0,%1,%2,%3}, {%4,%5,%6,%7}, {%8,%9}, {%0,%1,%2,%3};"
        : "+f"(c[0]), "+f"(c[1]), "+f"(c[2]), "+f"(c[3])
        : "r"(a[0]), "r"(a[1]), "r"(a[2]), "r"(a[3]), "r"(b[0]), "r"(b[1]));
}
__device__ __forceinline__ void split2(float a, float b, uint32_t& hi, uint32_t& lo) {
    __nv_bfloat16 ha = __float2bfloat16_rn(a);
    __nv_bfloat16 hb = __float2bfloat16_rn(b);
    __nv_bfloat16 la = __float2bfloat16_rn(a - __bfloat162float(ha));
    __nv_bfloat16 lb = __float2bfloat16_rn(b - __bfloat162float(hb));
    __nv_bfloat162 h2 = __nv_bfloat162(ha, hb);
    __nv_bfloat162 l2 = __nv_bfloat162(la, lb);
    hi = *(uint32_t*)&h2;
    lo = *(uint32_t*)&l2;
}

// ================= fp32 -> bf16 hi/lo split (elementwise) ====================
__global__ __launch_bounds__(256)
void split_kernel(const float* __restrict__ src, __nv_bfloat16* __restrict__ hi,
                  __nv_bfloat16* __restrict__ lo, int n)
{
    int i4 = blockIdx.x * blockDim.x + threadIdx.x;
    if (i4 * 4 >= n) return;
    float4 v = *(const float4*)(src + i4 * 4);
    uint32_t h0, l0, h1, l1;
    split2(v.x, v.y, h0, l0);
    split2(v.z, v.w, h1, l1);
    *(uint2*)(hi + i4 * 4) = make_uint2(h0, h1);
    *(uint2*)(lo + i4 * 4) = make_uint2(l0, l1);
}

// ========== tensor-core GEMM: C[M,N] = A[M,K] * B[N,K]^T =====================
// OM=0: fp32 C.   OM=1: bf16 hi/lo C.
// BM=BN=128, BK=32. 512 threads, 16 warps in 4(M)x4(N); warp tile 32x32.
// acc = 32 regs/thread -> ~100 total regs -> 4 warps/SMSP resident.
#define GBM 128
#define GBN 128
#define GBK 32
#define MAT_BYTES 8192
#define STAGE_BYTES 32768
#define GT_SMEM (3 * STAGE_BYTES)

template <int OM>
__global__ __launch_bounds__(512, 1)
void gemm_bf16s(const __nv_bfloat16* __restrict__ Ah, const __nv_bfloat16* __restrict__ Al,
                const __nv_bfloat16* __restrict__ Bh, const __nv_bfloat16* __restrict__ Bl,
                float* __restrict__ C, __nv_bfloat16* __restrict__ Ch,
                __nv_bfloat16* __restrict__ Cl, int N, int K)
{
    extern __shared__ char sm[];
    const uint32_t sbase = smem_u32(sm);
    const int tid  = threadIdx.x;
    const int wid  = tid >> 5;
    const int lane = tid & 31;
    const int bx = blockIdx.x;
    const int by = blockIdx.y;
    const int wm = wid >> 2;       // 0..3  (M)
    const int wn = wid & 3;        // 0..3  (N)

    const __nv_bfloat16* gsrc[4] = {
        Ah + (size_t)by * GBM * K, Al + (size_t)by * GBM * K,
        Bh + (size_t)bx * GBN * K, Bl + (size_t)bx * GBN * K };

    // per chunk: 4 mats x 512 x 16B; idx -> mat(2b), kc(2b), row(7b)
    auto prefetch = [&](int c) {
        const uint32_t sst = sbase + (uint32_t)(c % 3) * STAGE_BYTES;
        const int k0 = c * GBK;
#pragma unroll
        for (int i = 0; i < 4; i++) {
            int idx = i * 512 + tid;
            int mat = idx >> 9;
            int within = idx & 511;
            int kc  = within >> 7;
            int row = within & 127;
            const __nv_bfloat16* g = gsrc[mat] + (size_t)row * K + k0 + kc * 8;
            uint32_t s = sst + mat * MAT_BYTES + kc * 2048 + row * 16;
            cp_async16(s, g);
        }
        cp_commit();
    };

    const int subA = lane >> 3;
    const int rowoffA = (lane & 7) + (subA & 1) * 8;
    const int kcselA  = subA >> 1;
    const int rowoffB = (lane & 7) + ((lane >> 4) * 8);
    const int kcselB  = (lane >> 3) & 1;

    float acc[2][4][4];
#pragma unroll
    for (int mt = 0; mt < 2; mt++)
#pragma unroll
        for (int nt = 0; nt < 4; nt++)
#pragma unroll
            for (int q = 0; q < 4; q++) acc[mt][nt][q] = 0.f;

    const int KC = K / GBK;
    prefetch(0);
    prefetch(1);

    for (int c = 0; c < KC; c++) {
        cp_wait<1>();
        __syncthreads();
        if (c + 2 < KC) prefetch(c + 2);

        const uint32_t sst = sbase + (uint32_t)(c % 3) * STAGE_BYTES;
        const uint32_t aBaseHi = sst + 0 * MAT_BYTES;
        const uint32_t aBaseLo = sst + 1 * MAT_BYTES;
        const uint32_t bBaseHi = sst + 2 * MAT_BYTES;
        const uint32_t bBaseLo = sst + 3 * MAT_BYTES;

#pragma unroll
        for (int ks = 0; ks < 2; ks++) {
            uint32_t ah[2][4], al[2][4], bh[2][4], bl[2][4];
#pragma unroll
            for (int mt = 0; mt < 2; mt++) {
                uint32_t roff = (uint32_t)((ks * 2 + kcselA) * 2048 +
                                           (wm * 32 + mt * 16 + rowoffA) * 16);
                ldsm_x4(ah[mt], aBaseHi + roff);
                ldsm_x4(al[mt], aBaseLo + roff);
            }
#pragma unroll
            for (int np = 0; np < 2; np++) {
                uint32_t roff = (uint32_t)((ks * 2 + kcselB) * 2048 +
                                           (wn * 32 + np * 16 + rowoffB) * 16);
                ldsm_x4(bh[np], bBaseHi + roff);
                ldsm_x4(bl[np], bBaseLo + roff);
            }
            // 24 MMAs over 8 distinct accumulators
#pragma unroll
            for (int mt = 0; mt < 2; mt++)
#pragma unroll
                for (int np = 0; np < 2; np++)
#pragma unroll
                    for (int p = 0; p < 3; p++)
#pragma unroll
                        for (int j = 0; j < 2; j++) {
                            const uint32_t* ap = (p == 2) ? al[mt] : ah[mt];
                            const uint32_t* bp = (p == 1) ? &bl[np][j * 2]
                                                          : &bh[np][j * 2];
                            mma16816(acc[mt][np * 2 + j], ap, bp);
                        }
        }
        __syncthreads();
    }

    const int g  = lane >> 2;
    const int t2 = (lane & 3) * 2;
#pragma unroll
    for (int mt = 0; mt < 2; mt++) {
        int row0 = by * GBM + wm * 32 + mt * 16 + g;
#pragma unroll
        for (int nt = 0; nt < 4; nt++) {
            int col = bx * GBN + wn * 32 + nt * 8 + t2;
            if (OM == 0) {
                *(float2*)(C + (size_t)row0 * N + col) =
                    make_float2(acc[mt][nt][0], acc[mt][nt][1]);
                *(float2*)(C + (size_t)(row0 + 8) * N + col) =
                    make_float2(acc[mt][nt][2], acc[mt][nt][3]);
            } else {
                uint32_t h0, l0, h1, l1;
                split2(acc[mt][nt][0], acc[mt][nt][1], h0, l0);
                split2(acc[mt][nt][2], acc[mt][nt][3], h1, l1);
                *(uint32_t*)(Ch + (size_t)row0 * N + col) = h0;
                *(uint32_t*)(Cl + (size_t)row0 * N + col) = l0;
                *(uint32_t*)(Ch + (size_t)(row0 + 8) * N + col) = h1;
                *(uint32_t*)(Cl + (size_t)(row0 + 8) * N + col) = l1;
            }
        }
    }
}

// ============== tensor-core causal flash attention (bf16 hi/lo in) ===========
#define FA_SMEM 98304

__global__ __launch_bounds__(128, 1)
void flash_tc(const __nv_bfloat16* __restrict__ ph, const __nv_bfloat16* __restrict__ pl,
              __nv_bfloat16* __restrict__ ch, __nv_bfloat16* __restrict__ cl)
{
    extern __shared__ char smc[];
    const uint32_t sb = smem_u32(smc);
    const uint32_t sQH = sb,          sQL = sb + 16384;
    const uint32_t sKH = sb + 32768,  sKL = sb + 49152;
    const uint32_t sVH = sb + 65536,  sVL = sb + 81920;

    const int tid  = threadIdx.x;
    const int lane = tid & 31;
    const int wm   = tid >> 5;
    const int q0   = (int)(gridDim.x - 1 - blockIdx.x) * 64;
    const int h    = blockIdx.y;
    const int b    = blockIdx.z;
    const int g    = lane >> 2;
    const int t2   = (lane & 3) * 2;

    const size_t rowbase = (size_t)(b * SLEN) * H3 + h * HDIM;

    // ---- Q loads (group 0) ----
#pragma unroll
    for (int i = 0; i < 16; i++) {
        int item = i * 128 + tid;
        int mat = item >> 10;
        int within = item & 1023;
        int kcg = within >> 6;
        int row = within & 63;
        const __nv_bfloat16* src = (mat ? pl : ph) + rowbase + (size_t)(q0 + row) * H3 + kcg * 8;
        cp_async16((mat ? sQL : sQH) + kcg * 1024 + row * 16, src);
    }
    cp_commit();
    // ---- K tile 0 (group 1) ----
#pragma unroll
    for (int i = 0; i < 16; i++) {
        int item = i * 128 + tid;
        int mat = item >> 10;
        int within = item & 1023;
        int kcg = within >> 6;
        int row = within & 63;
        const __nv_bfloat16* src = (mat ? pl : ph) + rowbase + (size_t)row * H3 + HID + kcg * 8;
        cp_async16((mat ? sKL : sKH) + kcg * 1024 + row * 16, src);
    }
    cp_commit();

    cp_wait<1>();
    __syncthreads();

    const int rowoffA = (lane & 7) + ((lane >> 3) & 1) * 8;
    const int kcselA  = lane >> 4;
    const int rowoffB = (lane & 7) + (lane >> 4) * 8;
    const int kcselB  = (lane >> 3) & 1;

    uint32_t qh[8][4], ql[8][4];
#pragma unroll
    for (int k = 0; k < 8; k++) {
        uint32_t roff = (uint32_t)((2 * k + kcselA) * 1024 + (wm * 16 + rowoffA) * 16);
        ldsm_x4(qh[k], sQH + roff);
        ldsm_x4(ql[k], sQL + roff);
    }

    float m1 = -FLT_MAX, m2 = -FLT_MAX, l1 = 0.f, l2 = 0.f;
    float o[16][4];
#pragma unroll
    for (int nt = 0; nt < 16; nt++)
#pragma unroll
        for (int q = 0; q < 4; q++) o[nt][q] = 0.f;

    for (int k0 = 0; k0 <= q0; k0 += 64) {
        // ---- V loads for this tile ----
#pragma unroll
        for (int i = 0; i < 16; i++) {
            int item = i * 128 + tid;
            int mat = item >> 10;
            int within = item & 1023;
            int kcg = within >> 6;
            int row = within & 63;
            const __nv_bfloat16* src = (mat ? pl : ph) + rowbase +
                                       (size_t)(k0 + row) * H3 + 2 * HID + kcg * 8;
            cp_async16((mat ? sVL : sVH) + kcg * 1024 + row * 16, src);
        }
        cp_commit();

        cp_wait<1>();      // K ready
        __syncthreads();

        // ---- S = Q K^T ----
        float s[8][4];
#pragma unroll
        for (int nt = 0; nt < 8; nt++)
#pragma unroll
            for (int q = 0; q < 4; q++) s[nt][q] = 0.f;

#pragma unroll
        for (int k = 0; k < 8; k++) {
#pragma unroll
            for (int np = 0; np < 4; np++) {
                uint32_t roff = (uint32_t)((2 * k + kcselB) * 1024 + (np * 16 + rowoffB) * 16);
                uint32_t kh4[4], kl4[4];
                ldsm_x4(kh4, sKH + roff);
                ldsm_x4(kl4, sKL + roff);
#pragma unroll
                for (int p = 0; p < 3; p++)
#pragma unroll
                    for (int j = 0; j < 2; j++) {
                        const uint32_t* ap = (p == 2) ? ql[k] : qh[k];
                        const uint32_t* bp = (p == 1) ? &kl4[j * 2] : &kh4[j * 2];
                        mma16816(s[np * 2 + j], ap, bp);
                    }
            }
        }

        // ---- scale + causal mask ----
#pragma unroll
        for (int nt = 0; nt < 8; nt++)
#pragma unroll
            for (int q = 0; q < 4; q++) s[nt][q] *= SOFTMAX_SCALE;
        if (k0 == q0) {
            int r1 = q0 + wm * 16 + g, r2 = r1 + 8;
#pragma unroll
            for (int nt = 0; nt < 8; nt++) {
                int c0 = k0 + nt * 8 + t2;
                if (c0     > r1) s[nt][0] = -FLT_MAX;
                if (c0 + 1 > r1) s[nt][1] = -FLT_MAX;
                if (c0     > r2) s[nt][2] = -FLT_MAX;
                if (c0 + 1 > r2) s[nt][3] = -FLT_MAX;
            }
        }

        // ---- online softmax ----
        float tm1 = -FLT_MAX, tm2 = -FLT_MAX;
#pragma unroll
        for (int nt = 0; nt < 8; nt++) {
            tm1 = fmaxf(tm1, fmaxf(s[nt][0], s[nt][1]));
            tm2 = fmaxf(tm2, fmaxf(s[nt][2], s[nt][3]));
        }
        tm1 = fmaxf(tm1, __shfl_xor_sync(0xffffffffu, tm1, 1));
        tm1 = fmaxf(tm1, __shfl_xor_sync(0xffffffffu, tm1, 2));
        tm2 = fmaxf(tm2, __shfl_xor_sync(0xffffffffu, tm2, 1));
        tm2 = fmaxf(tm2, __shfl_xor_sync(0xffffffffu, tm2, 2));
        float nm1 = fmaxf(m1, tm1), nm2 = fmaxf(m2, tm2);
        float a1 = __expf(m1 - nm1), a2 = __expf(m2 - nm2);
        m1 = nm1; m2 = nm2;

        float rs1 = 0.f, rs2 = 0.f;
#pragma unroll
        for (int nt = 0; nt < 8; nt++) {
            s[nt][0] = __expf(s[nt][0] - nm1);
            s[nt][1] = __expf(s[nt][1] - nm1);
            s[nt][2] = __expf(s[nt][2] - nm2);
            s[nt][3] = __expf(s[nt][3] - nm2);
            rs1 += s[nt][0] + s[nt][1];
            rs2 += s[nt][2] + s[nt][3];
        }
        rs1 += __shfl_xor_sync(0xffffffffu, rs1, 1);
        rs1 += __shfl_xor_sync(0xffffffffu, rs1, 2);
        rs2 += __shfl_xor_sync(0xffffffffu, rs2, 1);
        rs2 += __shfl_xor_sync(0xffffffffu, rs2, 2);
        l1 = l1 * a1 + rs1;
        l2 = l2 * a2 + rs2;
#pragma unroll
        for (int nt = 0; nt < 16; nt++) {
            o[nt][0] *= a1; o[nt][1] *= a1;
            o[nt][2] *= a2; o[nt][3] *= a2;
        }

        // ---- P -> bf16 hi/lo fragments ----
        uint32_t hp01[8], hp23[8], lp01[8], lp23[8];
#pragma unroll
        for (int nt = 0; nt < 8; nt++) {
            split2(s[nt][0], s[nt][1], hp01[nt], lp01[nt]);
            split2(s[nt][2], s[nt][3], hp23[nt], lp23[nt]);
        }

        cp_wait<0>();       // V ready
        __syncthreads();
        if (k0 + 64 <= q0) {   // prefetch next K during PV
#pragma unroll
            for (int i = 0; i < 16; i++) {
                int item = i * 128 + tid;
                int mat = item >> 10;
                int within = item & 1023;
                int kcg = within >> 6;
                int row = within & 63;
                const __nv_bfloat16* src = (mat ? pl : ph) + rowbase +
                                           (size_t)(k0 + 64 + row) * H3 + HID + kcg * 8;
                cp_async16((mat ? sKL : sKH) + kcg * 1024 + row * 16, src);
            }
            cp_commit();
        }

        // ---- O += P V ----
#pragma unroll
        for (int kt = 0; kt < 4; kt++) {
            uint32_t ah4[4] = {hp01[2*kt], hp23[2*kt], hp01[2*kt+1], hp23[2*kt+1]};
            uint32_t al4[4] = {lp01[2*kt], lp23[2*kt], lp01[2*kt+1], lp23[2*kt+1]};
#pragma unroll
            for (int np = 0; np < 8; np++) {
                uint32_t roff = (uint32_t)((np * 2 + (lane >> 4)) * 1024 +
                                           (kt * 16 + ((lane >> 3) & 1) * 8 + (lane & 7)) * 16);
                uint32_t vh4[4], vl4[4];
                ldsm_x4_t(vh4, sVH + roff);
                ldsm_x4_t(vl4, sVL + roff);
#pragma unroll
                for (int p = 0; p < 3; p++)
#pragma unroll
                    for (int j = 0; j < 2; j++) {
                        const uint32_t* ap = (p == 2) ? al4 : ah4;
                        const uint32_t* bp = (p == 1) ? &vl4[j * 2] : &vh4[j * 2];
                        mma16816(o[np * 2 + j], ap, bp);
                    }
            }
        }
        __syncthreads();
    }

    // ---- finalize: write ctx as bf16 hi/lo ----
    float inv1 = 1.f / l1, inv2 = 1.f / l2;
    int r1 = q0 + wm * 16 + g;
    size_t base1 = (size_t)(b * SLEN + r1) * HID + h * HDIM;
    size_t base2 = base1 + 8 * HID;
#pragma unroll
    for (int nt = 0; nt < 16; nt++) {
        int col = nt * 8 + t2;
        uint32_t h0, l0, h1, l1w;
        split2(o[nt][0] * inv1, o[nt][1] * inv1, h0, l0);
        split2(o[nt][2] * inv2, o[nt][3] * inv2, h1, l1w);
        *(uint32_t*)(ch + base1 + col) = h0;
        *(uint32_t*)(cl + base1 + col) = l0;
        *(uint32_t*)(ch + base2 + col) = h1;
        *(uint32_t*)(cl + base2 + col) = l1w;
    }
}

// ============================ host entry =====================================
extern "C" void kernel_launch(void* const* d_in, const int* in_sizes, int n_in,
                              void* d_out, int out_size)
{
    const float* hidden = (const float*)d_in[0];
    const float* w_pack = (const float*)d_in[2];
    const float* w_o    = (const float*)d_in[3];
    float* out = (float*)d_out;

    __nv_bfloat16 *ph, *pl, *ch, *cl, *ah, *al, *bh, *bl;
    cudaGetSymbolAddress((void**)&ph, g_ph);
    cudaGetSymbolAddress((void**)&pl, g_pl);
    cudaGetSymbolAddress((void**)&ch, g_ch);
    cudaGetSymbolAddress((void**)&cl, g_cl);
    cudaGetSymbolAddress((void**)&ah, g_ah);
    cudaGetSymbolAddress((void**)&al, g_al);
    cudaGetSymbolAddress((void**)&bh, g_bh);
    cudaGetSymbolAddress((void**)&bl, g_bl);

    static bool attr_set = false;
    if (!attr_set) {
        cudaFuncSetAttribute(gemm_bf16s<0>, cudaFuncAttributeMaxDynamicSharedMemorySize, GT_SMEM);
        cudaFuncSetAttribute(gemm_bf16s<1>, cudaFuncAttributeMaxDynamicSharedMemorySize, GT_SMEM);
        cudaFuncSetAttribute(flash_tc,      cudaFuncAttributeMaxDynamicSharedMemorySize, FA_SMEM);
        attr_set = true;
    }

    // 1) split QKV inputs
    split_kernel<<<MROWS * HID / 4 / 256, 256>>>(hidden, ah, al, MROWS * HID);
    split_kernel<<<H3 * HID / 4 / 256, 256>>>(w_pack, bh, bl, H3 * HID);

    // 2) QKV projection -> bf16 hi/lo proj
    gemm_bf16s<1><<<dim3(H3 / GBN, MROWS / GBM), 512, GT_SMEM>>>(
        ah, al, bh, bl, nullptr, ph, pl, H3, HID);

    // 3) causal flash attention -> bf16 hi/lo ctx
    flash_tc<<<dim3(SLEN / 64, NHEADS, BATCH), 128, FA_SMEM>>>(ph, pl, ch, cl);

    // 4) split w_o, output projection -> fp32 out
    split_kernel<<<HID * HID / 4 / 256, 256>>>(w_o, bh, bl, HID * HID);
    gemm_bf16s<0><<<dim3(HID / GBN, MROWS / GBM), 512, GT_SMEM>>>(
        ch, cl, bh, bl, out, nullptr, nullptr, HID, HID);
}

// round 9
// speedup vs baseline: 3.3480x; 2.1818x over previous
#include <cuda_runtime.h>
#include <cuda_fp16.h>
#include <cfloat>
#include <cstdint>
#include <cstddef>

// Problem dims
#define BATCH   2
#define SLEN    2048
#define HID     2048
#define NHEADS  16
#define HDIM    128
#define H3      6144
#define MROWS   4096
#define SOFTMAX_SCALE 0.08838834764831845f   // 1/sqrt(128)

// ---------------- scratch (static device arrays; no allocations) -------------
__device__ __half g_p[(size_t)MROWS * H3];    // proj (fp16)
__device__ __half g_c[(size_t)MROWS * HID];   // ctx  (fp16)
__device__ __half g_a[(size_t)MROWS * HID];   // gemm A (hidden fp16)
__device__ __half g_b[(size_t)H3 * HID];      // gemm B (w_pack / w_o fp16)

// ===================== small PTX helpers =====================================
__device__ __forceinline__ uint32_t smem_u32(const void* p) {
    uint32_t a;
    asm("{ .reg .u64 t; cvta.to.shared.u64 t, %1; cvt.u32.u64 %0, t; }"
        : "=r"(a) : "l"(p));
    return a;
}
__device__ __forceinline__ void cp_async16(uint32_t saddr, const void* gaddr) {
    asm volatile("cp.async.cg.shared.global [%0], [%1], 16;"
                 :: "r"(saddr), "l"(gaddr) : "memory");
}
__device__ __forceinline__ void cp_commit() {
    asm volatile("cp.async.commit_group;" ::: "memory");
}
template <int N>
__device__ __forceinline__ void cp_wait() {
    asm volatile("cp.async.wait_group %0;" :: "n"(N) : "memory");
}
__device__ __forceinline__ void ldsm_x4(uint32_t* r, uint32_t addr) {
    asm volatile("ldmatrix.sync.aligned.m8n8.x4.shared.b16 {%0,%1,%2,%3}, [%4];"
                 : "=r"(r[0]), "=r"(r[1]), "=r"(r[2]), "=r"(r[3]) : "r"(addr));
}
__device__ __forceinline__ void ldsm_x4_t(uint32_t* r, uint32_t addr) {
    asm volatile("ldmatrix.sync.aligned.m8n8.x4.trans.shared.b16 {%0,%1,%2,%3}, [%4];"
                 : "=r"(r[0]), "=r"(r[1]), "=r"(r[2]), "=r"(r[3]) : "r"(addr));
}
__device__ __forceinline__ void mma16816h(float* c, const uint32_t* a, const uint32_t* b) {
    asm volatile(
        "mma.sync.aligned.m16n8k16.row.col.f32.f16.f16.f32 "
        "{%0,%1,%2,%3}, {%4,%5,%6,%7}, {%8,%9}, {%0,%1,%2,%3};"
        : "+f"(c[0]), "+f"(c[1]), "+f"(c[2]), "+f"(c[3])
        : "r"(a[0]), "r"(a[1]), "r"(a[2]), "r"(a[3]), "r"(b[0]), "r"(b[1]));
}
__device__ __forceinline__ uint32_t pack_h2(float a, float b) {
    __half2 h = __floats2half2_rn(a, b);
    return *(uint32_t*)&h;
}

// ================= fp32 -> fp16 convert (elementwise) ========================
__global__ __launch_bounds__(256)
void cvt_kernel(const float* __restrict__ src, __half* __restrict__ dst, int n)
{
    int i4 = blockIdx.x * blockDim.x + threadIdx.x;
    if (i4 * 4 >= n) return;
    float4 v = *(const float4*)(src + i4 * 4);
    *(uint2*)(dst + i4 * 4) = make_uint2(pack_h2(v.x, v.y), pack_h2(v.z, v.w));
}

// ========== tensor-core GEMM: C[M,N] = A[M,K] * B[N,K]^T (fp16 in) ==========
// OM=0: fp32 C.   OM=1: fp16 C.
// BM=BN=128, BK=32. 512 threads, 16 warps 4(M)x4(N); warp tile 32x32.
// single fp16 product, fp32 accumulate.
#define GBM 128
#define GBN 128
#define GBK 32
#define MAT_BYTES 8192                 // 128 rows x 32 cols x 2B
#define STAGE_BYTES 16384              // A + B
#define GT_SMEM (3 * STAGE_BYTES)      // 48KB

template <int OM>
__global__ __launch_bounds__(512, 1)
void gemm_f16(const __half* __restrict__ A, const __half* __restrict__ B,
              float* __restrict__ C, __half* __restrict__ Ch, int N, int K)
{
    extern __shared__ char sm[];
    const uint32_t sbase = smem_u32(sm);
    const int tid  = threadIdx.x;
    const int wid  = tid >> 5;
    const int lane = tid & 31;
    const int bx = blockIdx.x;
    const int by = blockIdx.y;
    const int wm = wid >> 2;       // 0..3  (M)
    const int wn = wid & 3;        // 0..3  (N)

    const __half* gA = A + (size_t)by * GBM * K;
    const __half* gB = B + (size_t)bx * GBN * K;

    // per chunk: 2 mats x (4 kc x 128 rows) = 1024 items; 2 per thread
    auto prefetch = [&](int c) {
        const uint32_t sst = sbase + (uint32_t)(c % 3) * STAGE_BYTES;
        const int k0 = c * GBK;
#pragma unroll
        for (int i = 0; i < 2; i++) {
            int idx = i * 512 + tid;
            int mat = idx >> 9;
            int within = idx & 511;
            int kc  = within >> 7;
            int row = within & 127;
            const __half* g = (mat ? gB : gA) + (size_t)row * K + k0 + kc * 8;
            uint32_t s = sst + mat * MAT_BYTES + kc * 2048 + row * 16;
            cp_async16(s, g);
        }
        cp_commit();
    };

    const int subA = lane >> 3;
    const int rowoffA = (lane & 7) + (subA & 1) * 8;
    const int kcselA  = subA >> 1;
    const int rowoffB = (lane & 7) + ((lane >> 4) * 8);
    const int kcselB  = (lane >> 3) & 1;

    float acc[2][4][4];
#pragma unroll
    for (int mt = 0; mt < 2; mt++)
#pragma unroll
        for (int nt = 0; nt < 4; nt++)
#pragma unroll
            for (int q = 0; q < 4; q++) acc[mt][nt][q] = 0.f;

    const int KC = K / GBK;
    prefetch(0);
    prefetch(1);

    for (int c = 0; c < KC; c++) {
        cp_wait<1>();
        __syncthreads();
        if (c + 2 < KC) prefetch(c + 2);

        const uint32_t sst = sbase + (uint32_t)(c % 3) * STAGE_BYTES;
        const uint32_t aBase = sst;
        const uint32_t bBase = sst + MAT_BYTES;

#pragma unroll
        for (int ks = 0; ks < 2; ks++) {
            uint32_t ah[2][4], bh[2][4];
#pragma unroll
            for (int mt = 0; mt < 2; mt++) {
                uint32_t roff = (uint32_t)((ks * 2 + kcselA) * 2048 +
                                           (wm * 32 + mt * 16 + rowoffA) * 16);
                ldsm_x4(ah[mt], aBase + roff);
            }
#pragma unroll
            for (int np = 0; np < 2; np++) {
                uint32_t roff = (uint32_t)((ks * 2 + kcselB) * 2048 +
                                           (wn * 32 + np * 16 + rowoffB) * 16);
                ldsm_x4(bh[np], bBase + roff);
            }
            // 8 MMAs over 8 distinct accumulators
#pragma unroll
            for (int mt = 0; mt < 2; mt++)
#pragma unroll
                for (int np = 0; np < 2; np++)
#pragma unroll
                    for (int j = 0; j < 2; j++)
                        mma16816h(acc[mt][np * 2 + j], ah[mt], &bh[np][j * 2]);
        }
        __syncthreads();
    }

    const int g  = lane >> 2;
    const int t2 = (lane & 3) * 2;
#pragma unroll
    for (int mt = 0; mt < 2; mt++) {
        int row0 = by * GBM + wm * 32 + mt * 16 + g;
#pragma unroll
        for (int nt = 0; nt < 4; nt++) {
            int col = bx * GBN + wn * 32 + nt * 8 + t2;
            if (OM == 0) {
                *(float2*)(C + (size_t)row0 * N + col) =
                    make_float2(acc[mt][nt][0], acc[mt][nt][1]);
                *(float2*)(C + (size_t)(row0 + 8) * N + col) =
                    make_float2(acc[mt][nt][2], acc[mt][nt][3]);
            } else {
                *(uint32_t*)(Ch + (size_t)row0 * N + col) =
                    pack_h2(acc[mt][nt][0], acc[mt][nt][1]);
                *(uint32_t*)(Ch + (size_t)(row0 + 8) * N + col) =
                    pack_h2(acc[mt][nt][2], acc[mt][nt][3]);
            }
        }
    }
}

// ============== tensor-core causal flash attention (fp16 in/out) =============
// CTA: 64 q-rows, 4 warps. BN=64 keys/iter.
// smem: Q K V each [kcg(16)][row(64)][16B] = 16KB -> 48KB total
#define FA_SMEM 49152

__global__ __launch_bounds__(128)
void flash_f16(const __half* __restrict__ p, __half* __restrict__ cc)
{
    extern __shared__ char smc[];
    const uint32_t sb = smem_u32(smc);
    const uint32_t sQ = sb;
    const uint32_t sK = sb + 16384;
    const uint32_t sV = sb + 32768;

    const int tid  = threadIdx.x;
    const int lane = tid & 31;
    const int wm   = tid >> 5;
    const int q0   = (int)(gridDim.x - 1 - blockIdx.x) * 64;
    const int h    = blockIdx.y;
    const int b    = blockIdx.z;
    const int g    = lane >> 2;
    const int t2   = (lane & 3) * 2;

    const size_t rowbase = (size_t)(b * SLEN) * H3 + h * HDIM;

    // ---- Q loads (group 0): 1024 items = 16 kcg x 64 rows ----
#pragma unroll
    for (int i = 0; i < 8; i++) {
        int item = i * 128 + tid;
        int kcg = item >> 6;
        int row = item & 63;
        cp_async16(sQ + kcg * 1024 + row * 16,
                   p + rowbase + (size_t)(q0 + row) * H3 + kcg * 8);
    }
    cp_commit();
    // ---- K tile 0 (group 1) ----
#pragma unroll
    for (int i = 0; i < 8; i++) {
        int item = i * 128 + tid;
        int kcg = item >> 6;
        int row = item & 63;
        cp_async16(sK + kcg * 1024 + row * 16,
                   p + rowbase + (size_t)row * H3 + HID + kcg * 8);
    }
    cp_commit();

    cp_wait<1>();
    __syncthreads();

    const int rowoffA = (lane & 7) + ((lane >> 3) & 1) * 8;
    const int kcselA  = lane >> 4;
    const int rowoffB = (lane & 7) + (lane >> 4) * 8;
    const int kcselB  = (lane >> 3) & 1;

    uint32_t qf[8][4];
#pragma unroll
    for (int k = 0; k < 8; k++) {
        uint32_t roff = (uint32_t)((2 * k + kcselA) * 1024 + (wm * 16 + rowoffA) * 16);
        ldsm_x4(qf[k], sQ + roff);
    }

    float m1 = -FLT_MAX, m2 = -FLT_MAX, l1 = 0.f, l2 = 0.f;
    float o[16][4];
#pragma unroll
    for (int nt = 0; nt < 16; nt++)
#pragma unroll
        for (int q = 0; q < 4; q++) o[nt][q] = 0.f;

    for (int k0 = 0; k0 <= q0; k0 += 64) {
        // ---- V loads for this tile ----
#pragma unroll
        for (int i = 0; i < 8; i++) {
            int item = i * 128 + tid;
            int kcg = item >> 6;
            int row = item & 63;
            cp_async16(sV + kcg * 1024 + row * 16,
                       p + rowbase + (size_t)(k0 + row) * H3 + 2 * HID + kcg * 8);
        }
        cp_commit();

        cp_wait<1>();      // K ready
        __syncthreads();

        // ---- S = Q K^T (single fp16 product) ----
        float s[8][4];
#pragma unroll
        for (int nt = 0; nt < 8; nt++)
#pragma unroll
            for (int q = 0; q < 4; q++) s[nt][q] = 0.f;

#pragma unroll
        for (int k = 0; k < 8; k++) {
#pragma unroll
            for (int np = 0; np < 4; np++) {
                uint32_t roff = (uint32_t)((2 * k + kcselB) * 1024 + (np * 16 + rowoffB) * 16);
                uint32_t kf[4];
                ldsm_x4(kf, sK + roff);
#pragma unroll
                for (int j = 0; j < 2; j++)
                    mma16816h(s[np * 2 + j], qf[k], &kf[j * 2]);
            }
        }

        // ---- scale + causal mask ----
#pragma unroll
        for (int nt = 0; nt < 8; nt++)
#pragma unroll
            for (int q = 0; q < 4; q++) s[nt][q] *= SOFTMAX_SCALE;
        if (k0 == q0) {
            int r1 = q0 + wm * 16 + g, r2 = r1 + 8;
#pragma unroll
            for (int nt = 0; nt < 8; nt++) {
                int c0 = k0 + nt * 8 + t2;
                if (c0     > r1) s[nt][0] = -FLT_MAX;
                if (c0 + 1 > r1) s[nt][1] = -FLT_MAX;
                if (c0     > r2) s[nt][2] = -FLT_MAX;
                if (c0 + 1 > r2) s[nt][3] = -FLT_MAX;
            }
        }

        // ---- online softmax ----
        float tm1 = -FLT_MAX, tm2 = -FLT_MAX;
#pragma unroll
        for (int nt = 0; nt < 8; nt++) {
            tm1 = fmaxf(tm1, fmaxf(s[nt][0], s[nt][1]));
            tm2 = fmaxf(tm2, fmaxf(s[nt][2], s[nt][3]));
        }
        tm1 = fmaxf(tm1, __shfl_xor_sync(0xffffffffu, tm1, 1));
        tm1 = fmaxf(tm1, __shfl_xor_sync(0xffffffffu, tm1, 2));
        tm2 = fmaxf(tm2, __shfl_xor_sync(0xffffffffu, tm2, 1));
        tm2 = fmaxf(tm2, __shfl_xor_sync(0xffffffffu, tm2, 2));
        float nm1 = fmaxf(m1, tm1), nm2 = fmaxf(m2, tm2);
        float a1 = __expf(m1 - nm1), a2 = __expf(m2 - nm2);
        m1 = nm1; m2 = nm2;

        float rs1 = 0.f, rs2 = 0.f;
#pragma unroll
        for (int nt = 0; nt < 8; nt++) {
            s[nt][0] = __expf(s[nt][0] - nm1);
            s[nt][1] = __expf(s[nt][1] - nm1);
            s[nt][2] = __expf(s[nt][2] - nm2);
            s[nt][3] = __expf(s[nt][3] - nm2);
            rs1 += s[nt][0] + s[nt][1];
            rs2 += s[nt][2] + s[nt][3];
        }
        rs1 += __shfl_xor_sync(0xffffffffu, rs1, 1);
        rs1 += __shfl_xor_sync(0xffffffffu, rs1, 2);
        rs2 += __shfl_xor_sync(0xffffffffu, rs2, 1);
        rs2 += __shfl_xor_sync(0xffffffffu, rs2, 2);
        l1 = l1 * a1 + rs1;
        l2 = l2 * a2 + rs2;
#pragma unroll
        for (int nt = 0; nt < 16; nt++) {
            o[nt][0] *= a1; o[nt][1] *= a1;
            o[nt][2] *= a2; o[nt][3] *= a2;
        }

        // ---- P -> fp16 fragments ----
        uint32_t p01[8], p23[8];
#pragma unroll
        for (int nt = 0; nt < 8; nt++) {
            p01[nt] = pack_h2(s[nt][0], s[nt][1]);
            p23[nt] = pack_h2(s[nt][2], s[nt][3]);
        }

        cp_wait<0>();       // V ready
        __syncthreads();
        if (k0 + 64 <= q0) {   // prefetch next K during PV
#pragma unroll
            for (int i = 0; i < 8; i++) {
                int item = i * 128 + tid;
                int kcg = item >> 6;
                int row = item & 63;
                cp_async16(sK + kcg * 1024 + row * 16,
                           p + rowbase + (size_t)(k0 + 64 + row) * H3 + HID + kcg * 8);
            }
            cp_commit();
        }

        // ---- O += P V (single fp16 product, V via ldmatrix.trans) ----
#pragma unroll
        for (int kt = 0; kt < 4; kt++) {
            uint32_t pa[4] = {p01[2*kt], p23[2*kt], p01[2*kt+1], p23[2*kt+1]};
#pragma unroll
            for (int np = 0; np < 8; np++) {
                uint32_t roff = (uint32_t)((np * 2 + (lane >> 4)) * 1024 +
                                           (kt * 16 + ((lane >> 3) & 1) * 8 + (lane & 7)) * 16);
                uint32_t vf[4];
                ldsm_x4_t(vf, sV + roff);
#pragma unroll
                for (int j = 0; j < 2; j++)
                    mma16816h(o[np * 2 + j], pa, &vf[j * 2]);
            }
        }
        __syncthreads();
    }

    // ---- finalize: write ctx as fp16 ----
    float inv1 = 1.f / l1, inv2 = 1.f / l2;
    int r1 = q0 + wm * 16 + g;
    size_t base1 = (size_t)(b * SLEN + r1) * HID + h * HDIM;
    size_t base2 = base1 + 8 * HID;
#pragma unroll
    for (int nt = 0; nt < 16; nt++) {
        int col = nt * 8 + t2;
        *(uint32_t*)(cc + base1 + col) = pack_h2(o[nt][0] * inv1, o[nt][1] * inv1);
        *(uint32_t*)(cc + base2 + col) = pack_h2(o[nt][2] * inv2, o[nt][3] * inv2);
    }
}

// ============================ host entry =====================================
extern "C" void kernel_launch(void* const* d_in, const int* in_sizes, int n_in,
                              void* d_out, int out_size)
{
    const float* hidden = (const float*)d_in[0];
    const float* w_pack = (const float*)d_in[2];
    const float* w_o    = (const float*)d_in[3];
    float* out = (float*)d_out;

    __half *p, *c, *a, *bb;
    cudaGetSymbolAddress((void**)&p,  g_p);
    cudaGetSymbolAddress((void**)&c,  g_c);
    cudaGetSymbolAddress((void**)&a,  g_a);
    cudaGetSymbolAddress((void**)&bb, g_b);

    static bool attr_set = false;
    if (!attr_set) {
        cudaFuncSetAttribute(gemm_f16<0>, cudaFuncAttributeMaxDynamicSharedMemorySize, GT_SMEM);
        cudaFuncSetAttribute(gemm_f16<1>, cudaFuncAttributeMaxDynamicSharedMemorySize, GT_SMEM);
        cudaFuncSetAttribute(flash_f16,   cudaFuncAttributeMaxDynamicSharedMemorySize, FA_SMEM);
        attr_set = true;
    }

    // 1) convert inputs to fp16
    cvt_kernel<<<MROWS * HID / 4 / 256, 256>>>(hidden, a, MROWS * HID);
    cvt_kernel<<<H3 * HID / 4 / 256, 256>>>(w_pack, bb, H3 * HID);

    // 2) QKV projection -> fp16 proj
    gemm_f16<1><<<dim3(H3 / GBN, MROWS / GBM), 512, GT_SMEM>>>(
        a, bb, nullptr, p, H3, HID);

    // 3) causal flash attention -> fp16 ctx
    flash_f16<<<dim3(SLEN / 64, NHEADS, BATCH), 128, FA_SMEM>>>(p, c);

    // 4) convert w_o, output projection -> fp32 out
    cvt_kernel<<<HID * HID / 4 / 256, 256>>>(w_o, bb, HID * HID);
    gemm_f16<0><<<dim3(HID / GBN, MROWS / GBM), 512, GT_SMEM>>>(
        c, bb, out, nullptr, HID, HID);
}

// round 10
// speedup vs baseline: 3.3651x; 1.0051x over previous
#include <cuda_runtime.h>
#include <cuda_fp16.h>
#include <cfloat>
#include <cstdint>
#include <cstddef>

// Problem dims
#define BATCH   2
#define SLEN    2048
#define HID     2048
#define NHEADS  16
#define HDIM    128
#define H3      6144
#define MROWS   4096
#define SOFTMAX_SCALE 0.08838834764831845f   // 1/sqrt(128)

// ---------------- scratch (static device arrays; no allocations) -------------
__device__ __half g_p[(size_t)MROWS * H3];    // proj (fp16)
__device__ __half g_c[(size_t)MROWS * HID];   // ctx  (fp16)
__device__ __half g_a[(size_t)MROWS * HID];   // gemm A (hidden fp16)
__device__ __half g_b[(size_t)H3 * HID];      // gemm B (w_pack / w_o fp16)

// ===================== small PTX helpers =====================================
__device__ __forceinline__ uint32_t smem_u32(const void* p) {
    uint32_t a;
    asm("{ .reg .u64 t; cvta.to.shared.u64 t, %1; cvt.u32.u64 %0, t; }"
        : "=r"(a) : "l"(p));
    return a;
}
__device__ __forceinline__ void cp_async16(uint32_t saddr, const void* gaddr) {
    asm volatile("cp.async.cg.shared.global [%0], [%1], 16;"
                 :: "r"(saddr), "l"(gaddr) : "memory");
}
__device__ __forceinline__ void cp_commit() {
    asm volatile("cp.async.commit_group;" ::: "memory");
}
template <int N>
__device__ __forceinline__ void cp_wait() {
    asm volatile("cp.async.wait_group %0;" :: "n"(N) : "memory");
}
__device__ __forceinline__ void ldsm_x4(uint32_t* r, uint32_t addr) {
    asm volatile("ldmatrix.sync.aligned.m8n8.x4.shared.b16 {%0,%1,%2,%3}, [%4];"
                 : "=r"(r[0]), "=r"(r[1]), "=r"(r[2]), "=r"(r[3]) : "r"(addr));
}
__device__ __forceinline__ void ldsm_x4_t(uint32_t* r, uint32_t addr) {
    asm volatile("ldmatrix.sync.aligned.m8n8.x4.trans.shared.b16 {%0,%1,%2,%3}, [%4];"
                 : "=r"(r[0]), "=r"(r[1]), "=r"(r[2]), "=r"(r[3]) : "r"(addr));
}
__device__ __forceinline__ void mma16816h(float* c, const uint32_t* a, const uint32_t* b) {
    asm volatile(
        "mma.sync.aligned.m16n8k16.row.col.f32.f16.f16.f32 "
        "{%0,%1,%2,%3}, {%4,%5,%6,%7}, {%8,%9}, {%0,%1,%2,%3};"
        : "+f"(c[0]), "+f"(c[1]), "+f"(c[2]), "+f"(c[3])
        : "r"(a[0]), "r"(a[1]), "r"(a[2]), "r"(a[3]), "r"(b[0]), "r"(b[1]));
}
__device__ __forceinline__ uint32_t pack_h2(float a, float b) {
    __half2 h = __floats2half2_rn(a, b);
    return *(uint32_t*)&h;
}

// ================= fp32 -> fp16 convert (elementwise) ========================
__global__ __launch_bounds__(256)
void cvt_kernel(const float* __restrict__ src, __half* __restrict__ dst, int n)
{
    int i4 = blockIdx.x * blockDim.x + threadIdx.x;
    if (i4 * 4 >= n) return;
    float4 v = *(const float4*)(src + i4 * 4);
    *(uint2*)(dst + i4 * 4) = make_uint2(pack_h2(v.x, v.y), pack_h2(v.z, v.w));
}

// ========== tensor-core GEMM: C[M,N] = A[M,K] * B[N,K]^T (fp16 in) ==========
// OM=0: fp32 C.   OM=1: fp16 C.
// BM=BN=128, BK=64. 512 threads, 16 warps 4(M)x4(N); warp tile 32x32.
// 3-stage cp.async ring, ONE barrier per chunk.
#define GBM 128
#define GBN 128
#define GBK 64
#define MAT_BYTES 16384                // 128 rows x 64 cols x 2B
#define STAGE_BYTES 32768              // A + B
#define GT_SMEM (3 * STAGE_BYTES)      // 96KB

template <int OM>
__global__ __launch_bounds__(512, 1)
void gemm_f16(const __half* __restrict__ A, const __half* __restrict__ B,
              float* __restrict__ C, __half* __restrict__ Ch, int N, int K)
{
    extern __shared__ char sm[];
    const uint32_t sbase = smem_u32(sm);
    const int tid  = threadIdx.x;
    const int wid  = tid >> 5;
    const int lane = tid & 31;
    const int bx = blockIdx.x;
    const int by = blockIdx.y;
    const int wm = wid >> 2;       // 0..3  (M)
    const int wn = wid & 3;        // 0..3  (N)

    const __half* gA = A + (size_t)by * GBM * K;
    const __half* gB = B + (size_t)bx * GBN * K;

    // per chunk: 2 mats x (8 kc x 128 rows) = 2048 items; 4 per thread
    auto prefetch = [&](int c) {
        const uint32_t sst = sbase + (uint32_t)(c % 3) * STAGE_BYTES;
        const int k0 = c * GBK;
#pragma unroll
        for (int i = 0; i < 4; i++) {
            int idx = i * 512 + tid;
            int mat = idx >> 10;
            int within = idx & 1023;
            int kc  = within >> 7;          // 0..7
            int row = within & 127;
            const __half* g = (mat ? gB : gA) + (size_t)row * K + k0 + kc * 8;
            uint32_t s = sst + mat * MAT_BYTES + kc * 2048 + row * 16;
            cp_async16(s, g);
        }
        cp_commit();
    };

    const int subA = lane >> 3;
    const int rowoffA = (lane & 7) + (subA & 1) * 8;
    const int kcselA  = subA >> 1;
    const int rowoffB = (lane & 7) + ((lane >> 4) * 8);
    const int kcselB  = (lane >> 3) & 1;

    float acc[2][4][4];
#pragma unroll
    for (int mt = 0; mt < 2; mt++)
#pragma unroll
        for (int nt = 0; nt < 4; nt++)
#pragma unroll
            for (int q = 0; q < 4; q++) acc[mt][nt][q] = 0.f;

    const int KC = K / GBK;
    prefetch(0);
    prefetch(1);

    for (int c = 0; c < KC; c++) {
        cp_wait<1>();
        __syncthreads();           // single barrier per chunk (3-stage ring)
        if (c + 2 < KC) prefetch(c + 2);

        const uint32_t sst = sbase + (uint32_t)(c % 3) * STAGE_BYTES;
        const uint32_t aBase = sst;
        const uint32_t bBase = sst + MAT_BYTES;

#pragma unroll
        for (int ks = 0; ks < 4; ks++) {   // 4 x 16 cols = 64
            uint32_t ah[2][4], bh[2][4];
#pragma unroll
            for (int mt = 0; mt < 2; mt++) {
                uint32_t roff = (uint32_t)((ks * 2 + kcselA) * 2048 +
                                           (wm * 32 + mt * 16 + rowoffA) * 16);
                ldsm_x4(ah[mt], aBase + roff);
            }
#pragma unroll
            for (int np = 0; np < 2; np++) {
                uint32_t roff = (uint32_t)((ks * 2 + kcselB) * 2048 +
                                           (wn * 32 + np * 16 + rowoffB) * 16);
                ldsm_x4(bh[np], bBase + roff);
            }
#pragma unroll
            for (int mt = 0; mt < 2; mt++)
#pragma unroll
                for (int np = 0; np < 2; np++)
#pragma unroll
                    for (int j = 0; j < 2; j++)
                        mma16816h(acc[mt][np * 2 + j], ah[mt], &bh[np][j * 2]);
        }
    }

    const int g  = lane >> 2;
    const int t2 = (lane & 3) * 2;
#pragma unroll
    for (int mt = 0; mt < 2; mt++) {
        int row0 = by * GBM + wm * 32 + mt * 16 + g;
#pragma unroll
        for (int nt = 0; nt < 4; nt++) {
            int col = bx * GBN + wn * 32 + nt * 8 + t2;
            if (OM == 0) {
                *(float2*)(C + (size_t)row0 * N + col) =
                    make_float2(acc[mt][nt][0], acc[mt][nt][1]);
                *(float2*)(C + (size_t)(row0 + 8) * N + col) =
                    make_float2(acc[mt][nt][2], acc[mt][nt][3]);
            } else {
                *(uint32_t*)(Ch + (size_t)row0 * N + col) =
                    pack_h2(acc[mt][nt][0], acc[mt][nt][1]);
                *(uint32_t*)(Ch + (size_t)(row0 + 8) * N + col) =
                    pack_h2(acc[mt][nt][2], acc[mt][nt][3]);
            }
        }
    }
}

// ============== tensor-core causal flash attention (fp16 in/out) =============
// CTA: 64 q-rows, 4 warps. BN=64 keys/iter.
// smem: Q K V each [kcg(16)][row(64)][16B] = 16KB -> 48KB total
#define FA_SMEM 49152

__global__ __launch_bounds__(128)
void flash_f16(const __half* __restrict__ p, __half* __restrict__ cc)
{
    extern __shared__ char smc[];
    const uint32_t sb = smem_u32(smc);
    const uint32_t sQ = sb;
    const uint32_t sK = sb + 16384;
    const uint32_t sV = sb + 32768;

    const int tid  = threadIdx.x;
    const int lane = tid & 31;
    const int wm   = tid >> 5;
    const int q0   = (int)(gridDim.x - 1 - blockIdx.x) * 64;
    const int h    = blockIdx.y;
    const int b    = blockIdx.z;
    const int g    = lane >> 2;
    const int t2   = (lane & 3) * 2;

    const size_t rowbase = (size_t)(b * SLEN) * H3 + h * HDIM;

    // ---- Q loads (group 0): 1024 items = 16 kcg x 64 rows ----
#pragma unroll
    for (int i = 0; i < 8; i++) {
        int item = i * 128 + tid;
        int kcg = item >> 6;
        int row = item & 63;
        cp_async16(sQ + kcg * 1024 + row * 16,
                   p + rowbase + (size_t)(q0 + row) * H3 + kcg * 8);
    }
    cp_commit();
    // ---- K tile 0 (group 1) ----
#pragma unroll
    for (int i = 0; i < 8; i++) {
        int item = i * 128 + tid;
        int kcg = item >> 6;
        int row = item & 63;
        cp_async16(sK + kcg * 1024 + row * 16,
                   p + rowbase + (size_t)row * H3 + HID + kcg * 8);
    }
    cp_commit();

    cp_wait<1>();
    __syncthreads();

    const int rowoffA = (lane & 7) + ((lane >> 3) & 1) * 8;
    const int kcselA  = lane >> 4;
    const int rowoffB = (lane & 7) + (lane >> 4) * 8;
    const int kcselB  = (lane >> 3) & 1;

    uint32_t qf[8][4];
#pragma unroll
    for (int k = 0; k < 8; k++) {
        uint32_t roff = (uint32_t)((2 * k + kcselA) * 1024 + (wm * 16 + rowoffA) * 16);
        ldsm_x4(qf[k], sQ + roff);
    }

    float m1 = -FLT_MAX, m2 = -FLT_MAX, l1 = 0.f, l2 = 0.f;
    float o[16][4];
#pragma unroll
    for (int nt = 0; nt < 16; nt++)
#pragma unroll
        for (int q = 0; q < 4; q++) o[nt][q] = 0.f;

    for (int k0 = 0; k0 <= q0; k0 += 64) {
        // ---- V loads for this tile ----
#pragma unroll
        for (int i = 0; i < 8; i++) {
            int item = i * 128 + tid;
            int kcg = item >> 6;
            int row = item & 63;
            cp_async16(sV + kcg * 1024 + row * 16,
                       p + rowbase + (size_t)(k0 + row) * H3 + 2 * HID + kcg * 8);
        }
        cp_commit();

        cp_wait<1>();      // K ready
        __syncthreads();

        // ---- S = Q K^T (single fp16 product) ----
        float s[8][4];
#pragma unroll
        for (int nt = 0; nt < 8; nt++)
#pragma unroll
            for (int q = 0; q < 4; q++) s[nt][q] = 0.f;

#pragma unroll
        for (int k = 0; k < 8; k++) {
#pragma unroll
            for (int np = 0; np < 4; np++) {
                uint32_t roff = (uint32_t)((2 * k + kcselB) * 1024 + (np * 16 + rowoffB) * 16);
                uint32_t kf[4];
                ldsm_x4(kf, sK + roff);
#pragma unroll
                for (int j = 0; j < 2; j++)
                    mma16816h(s[np * 2 + j], qf[k], &kf[j * 2]);
            }
        }

        // ---- scale + causal mask ----
#pragma unroll
        for (int nt = 0; nt < 8; nt++)
#pragma unroll
            for (int q = 0; q < 4; q++) s[nt][q] *= SOFTMAX_SCALE;
        if (k0 == q0) {
            int r1 = q0 + wm * 16 + g, r2 = r1 + 8;
#pragma unroll
            for (int nt = 0; nt < 8; nt++) {
                int c0 = k0 + nt * 8 + t2;
                if (c0     > r1) s[nt][0] = -FLT_MAX;
                if (c0 + 1 > r1) s[nt][1] = -FLT_MAX;
                if (c0     > r2) s[nt][2] = -FLT_MAX;
                if (c0 + 1 > r2) s[nt][3] = -FLT_MAX;
            }
        }

        // ---- online softmax ----
        float tm1 = -FLT_MAX, tm2 = -FLT_MAX;
#pragma unroll
        for (int nt = 0; nt < 8; nt++) {
            tm1 = fmaxf(tm1, fmaxf(s[nt][0], s[nt][1]));
            tm2 = fmaxf(tm2, fmaxf(s[nt][2], s[nt][3]));
        }
        tm1 = fmaxf(tm1, __shfl_xor_sync(0xffffffffu, tm1, 1));
        tm1 = fmaxf(tm1, __shfl_xor_sync(0xffffffffu, tm1, 2));
        tm2 = fmaxf(tm2, __shfl_xor_sync(0xffffffffu, tm2, 1));
        tm2 = fmaxf(tm2, __shfl_xor_sync(0xffffffffu, tm2, 2));
        float nm1 = fmaxf(m1, tm1), nm2 = fmaxf(m2, tm2);
        float a1 = __expf(m1 - nm1), a2 = __expf(m2 - nm2);
        m1 = nm1; m2 = nm2;

        float rs1 = 0.f, rs2 = 0.f;
#pragma unroll
        for (int nt = 0; nt < 8; nt++) {
            s[nt][0] = __expf(s[nt][0] - nm1);
            s[nt][1] = __expf(s[nt][1] - nm1);
            s[nt][2] = __expf(s[nt][2] - nm2);
            s[nt][3] = __expf(s[nt][3] - nm2);
            rs1 += s[nt][0] + s[nt][1];
            rs2 += s[nt][2] + s[nt][3];
        }
        rs1 += __shfl_xor_sync(0xffffffffu, rs1, 1);
        rs1 += __shfl_xor_sync(0xffffffffu, rs1, 2);
        rs2 += __shfl_xor_sync(0xffffffffu, rs2, 1);
        rs2 += __shfl_xor_sync(0xffffffffu, rs2, 2);
        l1 = l1 * a1 + rs1;
        l2 = l2 * a2 + rs2;
#pragma unroll
        for (int nt = 0; nt < 16; nt++) {
            o[nt][0] *= a1; o[nt][1] *= a1;
            o[nt][2] *= a2; o[nt][3] *= a2;
        }

        // ---- P -> fp16 fragments ----
        uint32_t p01[8], p23[8];
#pragma unroll
        for (int nt = 0; nt < 8; nt++) {
            p01[nt] = pack_h2(s[nt][0], s[nt][1]);
            p23[nt] = pack_h2(s[nt][2], s[nt][3]);
        }

        cp_wait<0>();       // V ready
        __syncthreads();
        if (k0 + 64 <= q0) {   // prefetch next K during PV
#pragma unroll
            for (int i = 0; i < 8; i++) {
                int item = i * 128 + tid;
                int kcg = item >> 6;
                int row = item & 63;
                cp_async16(sK + kcg * 1024 + row * 16,
                           p + rowbase + (size_t)(k0 + 64 + row) * H3 + HID + kcg * 8);
            }
            cp_commit();
        }

        // ---- O += P V (single fp16 product, V via ldmatrix.trans) ----
#pragma unroll
        for (int kt = 0; kt < 4; kt++) {
            uint32_t pa[4] = {p01[2*kt], p23[2*kt], p01[2*kt+1], p23[2*kt+1]};
#pragma unroll
            for (int np = 0; np < 8; np++) {
                uint32_t roff = (uint32_t)((np * 2 + (lane >> 4)) * 1024 +
                                           (kt * 16 + ((lane >> 3) & 1) * 8 + (lane & 7)) * 16);
                uint32_t vf[4];
                ldsm_x4_t(vf, sV + roff);
#pragma unroll
                for (int j = 0; j < 2; j++)
                    mma16816h(o[np * 2 + j], pa, &vf[j * 2]);
            }
        }
        __syncthreads();
    }

    // ---- finalize: write ctx as fp16 ----
    float inv1 = 1.f / l1, inv2 = 1.f / l2;
    int r1 = q0 + wm * 16 + g;
    size_t base1 = (size_t)(b * SLEN + r1) * HID + h * HDIM;
    size_t base2 = base1 + 8 * HID;
#pragma unroll
    for (int nt = 0; nt < 16; nt++) {
        int col = nt * 8 + t2;
        *(uint32_t*)(cc + base1 + col) = pack_h2(o[nt][0] * inv1, o[nt][1] * inv1);
        *(uint32_t*)(cc + base2 + col) = pack_h2(o[nt][2] * inv2, o[nt][3] * inv2);
    }
}

// ============================ host entry =====================================
extern "C" void kernel_launch(void* const* d_in, const int* in_sizes, int n_in,
                              void* d_out, int out_size)
{
    const float* hidden = (const float*)d_in[0];
    const float* w_pack = (const float*)d_in[2];
    const float* w_o    = (const float*)d_in[3];
    float* out = (float*)d_out;

    __half *p, *c, *a, *bb;
    cudaGetSymbolAddress((void**)&p,  g_p);
    cudaGetSymbolAddress((void**)&c,  g_c);
    cudaGetSymbolAddress((void**)&a,  g_a);
    cudaGetSymbolAddress((void**)&bb, g_b);

    static bool attr_set = false;
    if (!attr_set) {
        cudaFuncSetAttribute(gemm_f16<0>, cudaFuncAttributeMaxDynamicSharedMemorySize, GT_SMEM);
        cudaFuncSetAttribute(gemm_f16<1>, cudaFuncAttributeMaxDynamicSharedMemorySize, GT_SMEM);
        cudaFuncSetAttribute(flash_f16,   cudaFuncAttributeMaxDynamicSharedMemorySize, FA_SMEM);
        attr_set = true;
    }

    // 1) convert inputs to fp16
    cvt_kernel<<<MROWS * HID / 4 / 256, 256>>>(hidden, a, MROWS * HID);
    cvt_kernel<<<H3 * HID / 4 / 256, 256>>>(w_pack, bb, H3 * HID);

    // 2) QKV projection -> fp16 proj
    gemm_f16<1><<<dim3(H3 / GBN, MROWS / GBM), 512, GT_SMEM>>>(
        a, bb, nullptr, p, H3, HID);

    // 3) causal flash attention -> fp16 ctx
    flash_f16<<<dim3(SLEN / 64, NHEADS, BATCH), 128, FA_SMEM>>>(p, c);

    // 4) convert w_o, output projection -> fp32 out
    cvt_kernel<<<HID * HID / 4 / 256, 256>>>(w_o, bb, HID * HID);
    gemm_f16<0><<<dim3(HID / GBN, MROWS / GBM), 512, GT_SMEM>>>(
        c, bb, out, nullptr, HID, HID);
}

// round 11
// speedup vs baseline: 3.8308x; 1.1384x over previous
#include <cuda_runtime.h>
#include <cuda_fp16.h>
#include <cfloat>
#include <cstdint>
#include <cstddef>

// Problem dims
#define BATCH   2
#define SLEN    2048
#define HID     2048
#define NHEADS  16
#define HDIM    128
#define H3      6144
#define MROWS   4096
#define SOFTMAX_SCALE 0.08838834764831845f   // 1/sqrt(128)

// ---------------- scratch (static device arrays; no allocations) -------------
__device__ __half g_p[(size_t)MROWS * H3];    // proj (fp16)
__device__ __half g_c[(size_t)MROWS * HID];   // ctx  (fp16)
__device__ __half g_a[(size_t)MROWS * HID];   // gemm A (hidden fp16)
__device__ __half g_b[(size_t)H3 * HID];      // gemm B (w_pack / w_o fp16)

// ===================== small PTX helpers =====================================
__device__ __forceinline__ uint32_t smem_u32(const void* p) {
    uint32_t a;
    asm("{ .reg .u64 t; cvta.to.shared.u64 t, %1; cvt.u32.u64 %0, t; }"
        : "=r"(a) : "l"(p));
    return a;
}
__device__ __forceinline__ void cp_async16(uint32_t saddr, const void* gaddr) {
    asm volatile("cp.async.cg.shared.global [%0], [%1], 16;"
                 :: "r"(saddr), "l"(gaddr) : "memory");
}
__device__ __forceinline__ void cp_commit() {
    asm volatile("cp.async.commit_group;" ::: "memory");
}
template <int N>
__device__ __forceinline__ void cp_wait() {
    asm volatile("cp.async.wait_group %0;" :: "n"(N) : "memory");
}
__device__ __forceinline__ void ldsm_x4(uint32_t* r, uint32_t addr) {
    asm volatile("ldmatrix.sync.aligned.m8n8.x4.shared.b16 {%0,%1,%2,%3}, [%4];"
                 : "=r"(r[0]), "=r"(r[1]), "=r"(r[2]), "=r"(r[3]) : "r"(addr));
}
__device__ __forceinline__ void ldsm_x4_t(uint32_t* r, uint32_t addr) {
    asm volatile("ldmatrix.sync.aligned.m8n8.x4.trans.shared.b16 {%0,%1,%2,%3}, [%4];"
                 : "=r"(r[0]), "=r"(r[1]), "=r"(r[2]), "=r"(r[3]) : "r"(addr));
}
__device__ __forceinline__ void mma16816h(float* c, const uint32_t* a, const uint32_t* b) {
    asm volatile(
        "mma.sync.aligned.m16n8k16.row.col.f32.f16.f16.f32 "
        "{%0,%1,%2,%3}, {%4,%5,%6,%7}, {%8,%9}, {%0,%1,%2,%3};"
        : "+f"(c[0]), "+f"(c[1]), "+f"(c[2]), "+f"(c[3])
        : "r"(a[0]), "r"(a[1]), "r"(a[2]), "r"(a[3]), "r"(b[0]), "r"(b[1]));
}
__device__ __forceinline__ uint32_t pack_h2(float a, float b) {
    __half2 h = __floats2half2_rn(a, b);
    return *(uint32_t*)&h;
}

// ================= fp32 -> fp16 convert (elementwise) ========================
__global__ __launch_bounds__(256)
void cvt_kernel(const float* __restrict__ src, __half* __restrict__ dst, int n)
{
    int i4 = blockIdx.x * blockDim.x + threadIdx.x;
    if (i4 * 4 >= n) return;
    float4 v = *(const float4*)(src + i4 * 4);
    *(uint2*)(dst + i4 * 4) = make_uint2(pack_h2(v.x, v.y), pack_h2(v.z, v.w));
}

// ========== tensor-core GEMM: C[M,N] = A[M,K] * B[N,K]^T (fp16 in) ==========
// OM=0: fp32 C.   OM=1: fp16 C.
// BM=BN=128, BK=64. 256 threads, 8 warps 4(M)x2(N); warp tile 32x64.
// 3-stage cp.async ring, one barrier per chunk, 2 CTAs/SM.
#define GBM 128
#define GBN 128
#define GBK 64
#define MAT_BYTES 16384                // 128 rows x 64 cols x 2B
#define STAGE_BYTES 32768              // A + B
#define GT_SMEM (3 * STAGE_BYTES)      // 96KB

template <int OM>
__global__ __launch_bounds__(256, 2)
void gemm_f16(const __half* __restrict__ A, const __half* __restrict__ B,
              float* __restrict__ C, __half* __restrict__ Ch, int N, int K)
{
    extern __shared__ char sm[];
    const uint32_t sbase = smem_u32(sm);
    const int tid  = threadIdx.x;
    const int wid  = tid >> 5;
    const int lane = tid & 31;
    const int bx = blockIdx.x;
    const int by = blockIdx.y;
    const int wm = wid >> 1;       // 0..3  (M)
    const int wn = wid & 1;        // 0..1  (N)

    const __half* gA = A + (size_t)by * GBM * K;
    const __half* gB = B + (size_t)bx * GBN * K;

    // per chunk: 2 mats x (8 kc x 128 rows) = 2048 items; 8 per thread
    auto prefetch = [&](int c) {
        const uint32_t sst = sbase + (uint32_t)(c % 3) * STAGE_BYTES;
        const int k0 = c * GBK;
#pragma unroll
        for (int i = 0; i < 8; i++) {
            int idx = i * 256 + tid;
            int mat = idx >> 10;
            int within = idx & 1023;
            int kc  = within >> 7;          // 0..7
            int row = within & 127;
            const __half* g = (mat ? gB : gA) + (size_t)row * K + k0 + kc * 8;
            uint32_t s = sst + mat * MAT_BYTES + kc * 2048 + row * 16;
            cp_async16(s, g);
        }
        cp_commit();
    };

    const int subA = lane >> 3;
    const int rowoffA = (lane & 7) + (subA & 1) * 8;
    const int kcselA  = subA >> 1;
    const int rowoffB = (lane & 7) + ((lane >> 4) * 8);
    const int kcselB  = (lane >> 3) & 1;

    float acc[2][8][4];
#pragma unroll
    for (int mt = 0; mt < 2; mt++)
#pragma unroll
        for (int nt = 0; nt < 8; nt++)
#pragma unroll
            for (int q = 0; q < 4; q++) acc[mt][nt][q] = 0.f;

    const int KC = K / GBK;
    prefetch(0);
    prefetch(1);

    for (int c = 0; c < KC; c++) {
        cp_wait<1>();
        __syncthreads();           // single barrier per chunk (3-stage ring)
        if (c + 2 < KC) prefetch(c + 2);

        const uint32_t sst = sbase + (uint32_t)(c % 3) * STAGE_BYTES;
        const uint32_t aBase = sst;
        const uint32_t bBase = sst + MAT_BYTES;

#pragma unroll
        for (int ks = 0; ks < 4; ks++) {   // 4 x 16 cols = 64
            uint32_t ah[2][4], bh[4][4];
#pragma unroll
            for (int mt = 0; mt < 2; mt++) {
                uint32_t roff = (uint32_t)((ks * 2 + kcselA) * 2048 +
                                           (wm * 32 + mt * 16 + rowoffA) * 16);
                ldsm_x4(ah[mt], aBase + roff);
            }
#pragma unroll
            for (int np = 0; np < 4; np++) {
                uint32_t roff = (uint32_t)((ks * 2 + kcselB) * 2048 +
                                           (wn * 64 + np * 16 + rowoffB) * 16);
                ldsm_x4(bh[np], bBase + roff);
            }
            // 16 MMAs over 16 distinct accumulators
#pragma unroll
            for (int mt = 0; mt < 2; mt++)
#pragma unroll
                for (int np = 0; np < 4; np++)
#pragma unroll
                    for (int j = 0; j < 2; j++)
                        mma16816h(acc[mt][np * 2 + j], ah[mt], &bh[np][j * 2]);
        }
    }

    const int g  = lane >> 2;
    const int t2 = (lane & 3) * 2;
#pragma unroll
    for (int mt = 0; mt < 2; mt++) {
        int row0 = by * GBM + wm * 32 + mt * 16 + g;
#pragma unroll
        for (int nt = 0; nt < 8; nt++) {
            int col = bx * GBN + wn * 64 + nt * 8 + t2;
            if (OM == 0) {
                *(float2*)(C + (size_t)row0 * N + col) =
                    make_float2(acc[mt][nt][0], acc[mt][nt][1]);
                *(float2*)(C + (size_t)(row0 + 8) * N + col) =
                    make_float2(acc[mt][nt][2], acc[mt][nt][3]);
            } else {
                *(uint32_t*)(Ch + (size_t)row0 * N + col) =
                    pack_h2(acc[mt][nt][0], acc[mt][nt][1]);
                *(uint32_t*)(Ch + (size_t)(row0 + 8) * N + col) =
                    pack_h2(acc[mt][nt][2], acc[mt][nt][3]);
            }
        }
    }
}

// ============== tensor-core causal flash attention (fp16 in/out) =============
// CTA: 64 q-rows, 4 warps. BN=64 keys/iter.
// smem: Q K V each [kcg(16)][row(64)][16B] = 16KB -> 48KB total
#define FA_SMEM 49152

__global__ __launch_bounds__(128)
void flash_f16(const __half* __restrict__ p, __half* __restrict__ cc)
{
    extern __shared__ char smc[];
    const uint32_t sb = smem_u32(smc);
    const uint32_t sQ = sb;
    const uint32_t sK = sb + 16384;
    const uint32_t sV = sb + 32768;

    const int tid  = threadIdx.x;
    const int lane = tid & 31;
    const int wm   = tid >> 5;
    const int q0   = (int)(gridDim.x - 1 - blockIdx.x) * 64;
    const int h    = blockIdx.y;
    const int b    = blockIdx.z;
    const int g    = lane >> 2;
    const int t2   = (lane & 3) * 2;

    const size_t rowbase = (size_t)(b * SLEN) * H3 + h * HDIM;

    // ---- Q loads (group 0): 1024 items = 16 kcg x 64 rows ----
#pragma unroll
    for (int i = 0; i < 8; i++) {
        int item = i * 128 + tid;
        int kcg = item >> 6;
        int row = item & 63;
        cp_async16(sQ + kcg * 1024 + row * 16,
                   p + rowbase + (size_t)(q0 + row) * H3 + kcg * 8);
    }
    cp_commit();
    // ---- K tile 0 (group 1) ----
#pragma unroll
    for (int i = 0; i < 8; i++) {
        int item = i * 128 + tid;
        int kcg = item >> 6;
        int row = item & 63;
        cp_async16(sK + kcg * 1024 + row * 16,
                   p + rowbase + (size_t)row * H3 + HID + kcg * 8);
    }
    cp_commit();

    cp_wait<1>();
    __syncthreads();

    const int rowoffA = (lane & 7) + ((lane >> 3) & 1) * 8;
    const int kcselA  = lane >> 4;
    const int rowoffB = (lane & 7) + (lane >> 4) * 8;
    const int kcselB  = (lane >> 3) & 1;

    uint32_t qf[8][4];
#pragma unroll
    for (int k = 0; k < 8; k++) {
        uint32_t roff = (uint32_t)((2 * k + kcselA) * 1024 + (wm * 16 + rowoffA) * 16);
        ldsm_x4(qf[k], sQ + roff);
    }

    float m1 = -FLT_MAX, m2 = -FLT_MAX, l1 = 0.f, l2 = 0.f;
    float o[16][4];
#pragma unroll
    for (int nt = 0; nt < 16; nt++)
#pragma unroll
        for (int q = 0; q < 4; q++) o[nt][q] = 0.f;

    for (int k0 = 0; k0 <= q0; k0 += 64) {
        // ---- V loads for this tile ----
#pragma unroll
        for (int i = 0; i < 8; i++) {
            int item = i * 128 + tid;
            int kcg = item >> 6;
            int row = item & 63;
            cp_async16(sV + kcg * 1024 + row * 16,
                       p + rowbase + (size_t)(k0 + row) * H3 + 2 * HID + kcg * 8);
        }
        cp_commit();

        cp_wait<1>();      // K ready
        __syncthreads();

        // ---- S = Q K^T (single fp16 product) ----
        float s[8][4];
#pragma unroll
        for (int nt = 0; nt < 8; nt++)
#pragma unroll
            for (int q = 0; q < 4; q++) s[nt][q] = 0.f;

#pragma unroll
        for (int k = 0; k < 8; k++) {
#pragma unroll
            for (int np = 0; np < 4; np++) {
                uint32_t roff = (uint32_t)((2 * k + kcselB) * 1024 + (np * 16 + rowoffB) * 16);
                uint32_t kf[4];
                ldsm_x4(kf, sK + roff);
#pragma unroll
                for (int j = 0; j < 2; j++)
                    mma16816h(s[np * 2 + j], qf[k], &kf[j * 2]);
            }
        }

        // ---- scale + causal mask ----
#pragma unroll
        for (int nt = 0; nt < 8; nt++)
#pragma unroll
            for (int q = 0; q < 4; q++) s[nt][q] *= SOFTMAX_SCALE;
        if (k0 == q0) {
            int r1 = q0 + wm * 16 + g, r2 = r1 + 8;
#pragma unroll
            for (int nt = 0; nt < 8; nt++) {
                int c0 = k0 + nt * 8 + t2;
                if (c0     > r1) s[nt][0] = -FLT_MAX;
                if (c0 + 1 > r1) s[nt][1] = -FLT_MAX;
                if (c0     > r2) s[nt][2] = -FLT_MAX;
                if (c0 + 1 > r2) s[nt][3] = -FLT_MAX;
            }
        }

        // ---- online softmax ----
        float tm1 = -FLT_MAX, tm2 = -FLT_MAX;
#pragma unroll
        for (int nt = 0; nt < 8; nt++) {
            tm1 = fmaxf(tm1, fmaxf(s[nt][0], s[nt][1]));
            tm2 = fmaxf(tm2, fmaxf(s[nt][2], s[nt][3]));
        }
        tm1 = fmaxf(tm1, __shfl_xor_sync(0xffffffffu, tm1, 1));
        tm1 = fmaxf(tm1, __shfl_xor_sync(0xffffffffu, tm1, 2));
        tm2 = fmaxf(tm2, __shfl_xor_sync(0xffffffffu, tm2, 1));
        tm2 = fmaxf(tm2, __shfl_xor_sync(0xffffffffu, tm2, 2));
        float nm1 = fmaxf(m1, tm1), nm2 = fmaxf(m2, tm2);
        float a1 = __expf(m1 - nm1), a2 = __expf(m2 - nm2);
        m1 = nm1; m2 = nm2;

        float rs1 = 0.f, rs2 = 0.f;
#pragma unroll
        for (int nt = 0; nt < 8; nt++) {
            s[nt][0] = __expf(s[nt][0] - nm1);
            s[nt][1] = __expf(s[nt][1] - nm1);
            s[nt][2] = __expf(s[nt][2] - nm2);
            s[nt][3] = __expf(s[nt][3] - nm2);
            rs1 += s[nt][0] + s[nt][1];
            rs2 += s[nt][2] + s[nt][3];
        }
        rs1 += __shfl_xor_sync(0xffffffffu, rs1, 1);
        rs1 += __shfl_xor_sync(0xffffffffu, rs1, 2);
        rs2 += __shfl_xor_sync(0xffffffffu, rs2, 1);
        rs2 += __shfl_xor_sync(0xffffffffu, rs2, 2);
        l1 = l1 * a1 + rs1;
        l2 = l2 * a2 + rs2;
#pragma unroll
        for (int nt = 0; nt < 16; nt++) {
            o[nt][0] *= a1; o[nt][1] *= a1;
            o[nt][2] *= a2; o[nt][3] *= a2;
        }

        // ---- P -> fp16 fragments ----
        uint32_t p01[8], p23[8];
#pragma unroll
        for (int nt = 0; nt < 8; nt++) {
            p01[nt] = pack_h2(s[nt][0], s[nt][1]);
            p23[nt] = pack_h2(s[nt][2], s[nt][3]);
        }

        cp_wait<0>();       // V ready
        __syncthreads();
        if (k0 + 64 <= q0) {   // prefetch next K during PV
#pragma unroll
            for (int i = 0; i < 8; i++) {
                int item = i * 128 + tid;
                int kcg = item >> 6;
                int row = item & 63;
                cp_async16(sK + kcg * 1024 + row * 16,
                           p + rowbase + (size_t)(k0 + 64 + row) * H3 + HID + kcg * 8);
            }
            cp_commit();
        }

        // ---- O += P V (single fp16 product, V via ldmatrix.trans) ----
#pragma unroll
        for (int kt = 0; kt < 4; kt++) {
            uint32_t pa[4] = {p01[2*kt], p23[2*kt], p01[2*kt+1], p23[2*kt+1]};
#pragma unroll
            for (int np = 0; np < 8; np++) {
                uint32_t roff = (uint32_t)((np * 2 + (lane >> 4)) * 1024 +
                                           (kt * 16 + ((lane >> 3) & 1) * 8 + (lane & 7)) * 16);
                uint32_t vf[4];
                ldsm_x4_t(vf, sV + roff);
#pragma unroll
                for (int j = 0; j < 2; j++)
                    mma16816h(o[np * 2 + j], pa, &vf[j * 2]);
            }
        }
        __syncthreads();
    }

    // ---- finalize: write ctx as fp16 ----
    float inv1 = 1.f / l1, inv2 = 1.f / l2;
    int r1 = q0 + wm * 16 + g;
    size_t base1 = (size_t)(b * SLEN + r1) * HID + h * HDIM;
    size_t base2 = base1 + 8 * HID;
#pragma unroll
    for (int nt = 0; nt < 16; nt++) {
        int col = nt * 8 + t2;
        *(uint32_t*)(cc + base1 + col) = pack_h2(o[nt][0] * inv1, o[nt][1] * inv1);
        *(uint32_t*)(cc + base2 + col) = pack_h2(o[nt][2] * inv2, o[nt][3] * inv2);
    }
}

// ============================ host entry =====================================
extern "C" void kernel_launch(void* const* d_in, const int* in_sizes, int n_in,
                              void* d_out, int out_size)
{
    const float* hidden = (const float*)d_in[0];
    const float* w_pack = (const float*)d_in[2];
    const float* w_o    = (const float*)d_in[3];
    float* out = (float*)d_out;

    __half *p, *c, *a, *bb;
    cudaGetSymbolAddress((void**)&p,  g_p);
    cudaGetSymbolAddress((void**)&c,  g_c);
    cudaGetSymbolAddress((void**)&a,  g_a);
    cudaGetSymbolAddress((void**)&bb, g_b);

    static bool attr_set = false;
    if (!attr_set) {
        cudaFuncSetAttribute(gemm_f16<0>, cudaFuncAttributeMaxDynamicSharedMemorySize, GT_SMEM);
        cudaFuncSetAttribute(gemm_f16<1>, cudaFuncAttributeMaxDynamicSharedMemorySize, GT_SMEM);
        cudaFuncSetAttribute(flash_f16,   cudaFuncAttributeMaxDynamicSharedMemorySize, FA_SMEM);
        attr_set = true;
    }

    // 1) convert inputs to fp16
    cvt_kernel<<<MROWS * HID / 4 / 256, 256>>>(hidden, a, MROWS * HID);
    cvt_kernel<<<H3 * HID / 4 / 256, 256>>>(w_pack, bb, H3 * HID);

    // 2) QKV projection -> fp16 proj
    gemm_f16<1><<<dim3(H3 / GBN, MROWS / GBM), 256, GT_SMEM>>>(
        a, bb, nullptr, p, H3, HID);

    // 3) causal flash attention -> fp16 ctx
    flash_f16<<<dim3(SLEN / 64, NHEADS, BATCH), 128, FA_SMEM>>>(p, c);

    // 4) convert w_o, output projection -> fp32 out
    cvt_kernel<<<HID * HID / 4 / 256, 256>>>(w_o, bb, HID * HID);
    gemm_f16<0><<<dim3(HID / GBN, MROWS / GBM), 256, GT_SMEM>>>(
        c, bb, out, nullptr, HID, HID);
}